// round 1
// baseline (speedup 1.0000x reference)
#include <cuda_runtime.h>

#define N_NODES 40000
#define N_EDGES 640000
#define C_DIM   128
#define OUT_CH  64

// ---------------- device scratch (no allocations allowed) ----------------
__device__ float g_agg[N_NODES * C_DIM];
__device__ float g_cnt[N_NODES];
__device__ float g_h1[N_NODES * C_DIM];
__device__ float g_h2[N_NODES * C_DIM];
__device__ float g_w1lT[C_DIM * C_DIM];
__device__ float g_w1rT[C_DIM * C_DIM];
__device__ float g_w2lT[C_DIM * C_DIM];
__device__ float g_w2rT[C_DIM * C_DIM];
__device__ float g_waT[C_DIM * OUT_CH];
__device__ int   g_is64;

// ---------------- index dtype detection ----------------
// int64 little-endian data for values < 2^32 looks like [lo,0,lo,0,...] as int32.
// For genuine int32 node indices (random in [0,40000)), 64 consecutive zero
// high-words have probability ~ (1/40000)^64 == never.
__global__ void detect_kernel(const int* ei) {
    if (blockIdx.x == 0 && threadIdx.x == 0) {
        bool is64 = true;
        for (int i = 0; i < 64; i++) {
            int lo = ei[2 * i];
            int hi = ei[2 * i + 1];
            if (hi != 0 || (unsigned)lo >= (unsigned)N_NODES) { is64 = false; break; }
        }
        g_is64 = is64 ? 1 : 0;
    }
}

__device__ __forceinline__ int load_idx(const void* ei, int pos, int is64) {
    if (is64) return (int)((const long long*)ei)[pos];
    return ((const int*)ei)[pos];
}

// ---------------- utility kernels ----------------
__global__ void zero_kernel(float* __restrict__ p, int n) {
    int i = blockIdx.x * blockDim.x + threadIdx.x;
    int stride = gridDim.x * blockDim.x;
    for (; i < n; i += stride) p[i] = 0.0f;
}

// out[c*rows + o] = in[o*cols + c]
__global__ void transpose_kernel(const float* __restrict__ in, float* __restrict__ out,
                                 int rows, int cols) {
    int idx = blockIdx.x * blockDim.x + threadIdx.x;
    if (idx < rows * cols) {
        int o = idx / cols;
        int c = idx - o * cols;
        out[c * rows + o] = in[idx];
    }
}

__global__ void count_kernel(const void* __restrict__ ei) {
    int e = blockIdx.x * blockDim.x + threadIdx.x;
    if (e >= N_EDGES) return;
    int is64 = g_is64;
    int dst = load_idx(ei, N_EDGES + e, is64);
    atomicAdd(&g_cnt[dst], 1.0f);
}

// one warp per edge: gather 128 floats of x[src], atomic-add into g_agg[dst]
__global__ void scatter_kernel(const void* __restrict__ ei, const float* __restrict__ xin) {
    int gt = blockIdx.x * blockDim.x + threadIdx.x;
    int e = gt >> 5;
    int lane = gt & 31;
    if (e >= N_EDGES) return;
    int is64 = g_is64;
    int src = load_idx(ei, e, is64);
    int dst = load_idx(ei, N_EDGES + e, is64);
    float4 v = ((const float4*)(xin + (size_t)src * C_DIM))[lane];
    float* dr = g_agg + (size_t)dst * C_DIM + lane * 4;
    atomicAdd(dr + 0, v.x);
    atomicAdd(dr + 1, v.y);
    atomicAdd(dr + 2, v.z);
    atomicAdd(dr + 3, v.w);
}

// ---------------- fused SAGE linear: out = relu(mean@wl^T + bl + x@wr^T) ----------------
// 128 threads/block, 32 nodes/block. Thread tile: 4 outputs x 8 nodes.
// wlT/wrT are pre-transposed to [c][o] so shared staging is conflict-free.
__global__ __launch_bounds__(128) void sage_kernel(
    const float* __restrict__ xin,
    const float* __restrict__ wlT, const float* __restrict__ wrT,
    const float* __restrict__ bl,
    float* __restrict__ out)
{
    __shared__ float s_m[32][32];
    __shared__ float s_x[32][32];
    __shared__ float s_wl[32][128];
    __shared__ float s_wr[32][128];
    __shared__ float s_rc[32];

    const int t = threadIdx.x;
    const int node0 = blockIdx.x * 32;
    const int o_base = (t & 31) * 4;    // lane -> 4 consecutive outputs (vector LDS)
    const int n_base = (t >> 5) * 8;    // warp-uniform -> broadcast LDS

    if (t < 32) {
        float c = g_cnt[node0 + t];
        s_rc[t] = 1.0f / fmaxf(c, 1.0f);
    }
    __syncthreads();

    float acc[8][4];
    float b0 = bl[o_base + 0], b1 = bl[o_base + 1], b2 = bl[o_base + 2], b3 = bl[o_base + 3];
#pragma unroll
    for (int i = 0; i < 8; i++) { acc[i][0] = b0; acc[i][1] = b1; acc[i][2] = b2; acc[i][3] = b3; }

    for (int ct = 0; ct < C_DIM; ct += 32) {
        // input tiles: 32 nodes x 32 channels, 8 elems/thread, coalesced
#pragma unroll
        for (int k = 0; k < 8; k++) {
            int idx = t + k * 128;
            int n = idx >> 5, c = idx & 31;
            int g = (node0 + n) * C_DIM + ct + c;
            s_m[n][c] = g_agg[g] * s_rc[n];
            s_x[n][c] = xin[g];
        }
        // weight tiles: [c][o], coalesced global + conflict-free shared stores
#pragma unroll
        for (int k = 0; k < 32; k++) {
            int idx = t + k * 128;
            int c = idx >> 7, o = idx & 127;
            s_wl[c][o] = wlT[(ct + c) * C_DIM + o];
            s_wr[c][o] = wrT[(ct + c) * C_DIM + o];
        }
        __syncthreads();

#pragma unroll
        for (int cc = 0; cc < 32; cc++) {
            float4 wl = *(const float4*)&s_wl[cc][o_base];
            float4 wr = *(const float4*)&s_wr[cc][o_base];
#pragma unroll
            for (int i = 0; i < 8; i++) {
                float m = s_m[n_base + i][cc];
                float xx = s_x[n_base + i][cc];
                acc[i][0] += m * wl.x + xx * wr.x;
                acc[i][1] += m * wl.y + xx * wr.y;
                acc[i][2] += m * wl.z + xx * wr.z;
                acc[i][3] += m * wl.w + xx * wr.w;
            }
        }
        __syncthreads();
    }

#pragma unroll
    for (int i = 0; i < 8; i++) {
        int n = node0 + n_base + i;
#pragma unroll
        for (int j = 0; j < 4; j++)
            out[n * C_DIM + o_base + j] = fmaxf(acc[i][j], 0.0f);
    }
}

// ---------------- head: logits = h@wa^T + ba ; values = h@wc^T + bc ----------------
// 256 threads/block, 32 nodes/block. logits thread tile: 1 output x 8 nodes.
__global__ __launch_bounds__(256) void head_kernel(
    const float* __restrict__ h,
    const float* __restrict__ waT, const float* __restrict__ ba,
    const float* __restrict__ wc, const float* __restrict__ bc,
    float* __restrict__ out)
{
    __shared__ float s_h[32][129];  // pad -> conflict-free column walk for values
    const int t = threadIdx.x;
    const int node0 = blockIdx.x * 32;

#pragma unroll
    for (int k = 0; k < 16; k++) {
        int idx = t + k * 256;
        int n = idx >> 7, c = idx & 127;
        s_h[n][c] = h[(node0 + n) * C_DIM + c];
    }
    __syncthreads();

    const int o = t & 63;
    const int n_base = (t >> 6) * 8;
    float acc[8];
    float bb = ba[o];
#pragma unroll
    for (int i = 0; i < 8; i++) acc[i] = bb;

    for (int c = 0; c < C_DIM; c++) {
        float w = waT[c * OUT_CH + o];   // coalesced, L1-resident (32 KB)
#pragma unroll
        for (int i = 0; i < 8; i++) acc[i] += s_h[n_base + i][c] * w;
    }
#pragma unroll
    for (int i = 0; i < 8; i++)
        out[(size_t)(node0 + n_base + i) * OUT_CH + o] = acc[i];

    // critic value: one thread per node
    if (t < 32) {
        float v = bc[0];
        for (int c = 0; c < C_DIM; c++) v += s_h[t][c] * wc[c];
        out[(size_t)N_NODES * OUT_CH + node0 + t] = v;
    }
}

// ---------------- launch ----------------
extern "C" void kernel_launch(void* const* d_in, const int* in_sizes, int n_in,
                              void* d_out, int out_size) {
    const float* x   = (const float*)d_in[0];
    const void*  ei  = d_in[1];
    const float* w1l = (const float*)d_in[2];
    const float* b1l = (const float*)d_in[3];
    const float* w1r = (const float*)d_in[4];
    const float* w2l = (const float*)d_in[5];
    const float* b2l = (const float*)d_in[6];
    const float* w2r = (const float*)d_in[7];
    const float* wa  = (const float*)d_in[8];
    const float* ba  = (const float*)d_in[9];
    const float* wc  = (const float*)d_in[10];
    const float* bc  = (const float*)d_in[11];
    float* out = (float*)d_out;

    float *agg, *cnt, *h1, *h2, *w1lT, *w1rT, *w2lT, *w2rT, *waT;
    cudaGetSymbolAddress((void**)&agg,  g_agg);
    cudaGetSymbolAddress((void**)&cnt,  g_cnt);
    cudaGetSymbolAddress((void**)&h1,   g_h1);
    cudaGetSymbolAddress((void**)&h2,   g_h2);
    cudaGetSymbolAddress((void**)&w1lT, g_w1lT);
    cudaGetSymbolAddress((void**)&w1rT, g_w1rT);
    cudaGetSymbolAddress((void**)&w2lT, g_w2lT);
    cudaGetSymbolAddress((void**)&w2rT, g_w2rT);
    cudaGetSymbolAddress((void**)&waT,  g_waT);

    detect_kernel<<<1, 32>>>((const int*)ei);

    transpose_kernel<<<(C_DIM * C_DIM + 255) / 256, 256>>>(w1l, w1lT, C_DIM, C_DIM);
    transpose_kernel<<<(C_DIM * C_DIM + 255) / 256, 256>>>(w1r, w1rT, C_DIM, C_DIM);
    transpose_kernel<<<(C_DIM * C_DIM + 255) / 256, 256>>>(w2l, w2lT, C_DIM, C_DIM);
    transpose_kernel<<<(C_DIM * C_DIM + 255) / 256, 256>>>(w2r, w2rT, C_DIM, C_DIM);
    transpose_kernel<<<(OUT_CH * C_DIM + 255) / 256, 256>>>(wa, waT, OUT_CH, C_DIM);

    // degree counts (graph is identical for both layers -> compute once)
    zero_kernel<<<(N_NODES + 255) / 256, 256>>>(cnt, N_NODES);
    count_kernel<<<(N_EDGES + 255) / 256, 256>>>(ei);

    const int scatter_blocks = (N_EDGES * 32 + 255) / 256;

    // ---- layer 1 ----
    zero_kernel<<<(N_NODES * C_DIM + 255) / 256, 256>>>(agg, N_NODES * C_DIM);
    scatter_kernel<<<scatter_blocks, 256>>>(ei, x);
    sage_kernel<<<N_NODES / 32, 128>>>(x, w1lT, w1rT, b1l, h1);

    // ---- layer 2 ----
    zero_kernel<<<(N_NODES * C_DIM + 255) / 256, 256>>>(agg, N_NODES * C_DIM);
    scatter_kernel<<<scatter_blocks, 256>>>(ei, h1);
    sage_kernel<<<N_NODES / 32, 128>>>(h1, w2lT, w2rT, b2l, h2);

    // ---- heads ----
    head_kernel<<<N_NODES / 32, 256>>>(h2, waT, ba, wc, bc, out);
}

// round 2
// speedup vs baseline: 1.9021x; 1.9021x over previous
#include <cuda_runtime.h>

#define N_NODES 40000
#define N_EDGES 640000
#define C_DIM   128
#define OUT_CH  64

// ---------------- device scratch (no allocations allowed) ----------------
__device__ float g_mean[N_NODES * C_DIM];
__device__ float g_h1[N_NODES * C_DIM];
__device__ float g_h2[N_NODES * C_DIM];
__device__ int   g_cnt[N_NODES];
__device__ int   g_offs[N_NODES + 1];
__device__ int   g_cursor[N_NODES];
__device__ int   g_csr_src[N_EDGES];
__device__ float g_w1lT[C_DIM * C_DIM];
__device__ float g_w1rT[C_DIM * C_DIM];
__device__ float g_w2lT[C_DIM * C_DIM];
__device__ float g_w2rT[C_DIM * C_DIM];
__device__ float g_waT[C_DIM * OUT_CH];
__device__ int   g_is64;

// ---------------- packed f32x2 helpers ----------------
#define FMA2(d, a, b) asm("fma.rn.f32x2 %0, %1, %2, %0;" : "+l"(d) : "l"(a), "l"(b))

__device__ __forceinline__ unsigned long long pack2(float lo, float hi) {
    unsigned long long r;
    asm("mov.b64 %0, {%1, %2};" : "=l"(r) : "f"(lo), "f"(hi));
    return r;
}
__device__ __forceinline__ float2 unpack2(unsigned long long v) {
    float2 f;
    asm("mov.b64 {%0, %1}, %2;" : "=f"(f.x), "=f"(f.y) : "l"(v));
    return f;
}

// ---------------- index dtype detection ----------------
__global__ void detect_kernel(const int* ei) {
    if (blockIdx.x == 0 && threadIdx.x == 0) {
        bool is64 = true;
        for (int i = 0; i < 64; i++) {
            int lo = ei[2 * i];
            int hi = ei[2 * i + 1];
            if (hi != 0 || (unsigned)lo >= (unsigned)N_NODES) { is64 = false; break; }
        }
        g_is64 = is64 ? 1 : 0;
    }
}

__device__ __forceinline__ int load_idx(const void* ei, int pos, int is64) {
    if (is64) return (int)((const long long*)ei)[pos];
    return ((const int*)ei)[pos];
}

// ---------------- prep: all 5 weight transposes in one kernel ----------------
__global__ void prep_kernel(const float* __restrict__ w1l, const float* __restrict__ w1r,
                            const float* __restrict__ w2l, const float* __restrict__ w2r,
                            const float* __restrict__ wa,
                            float* __restrict__ w1lT, float* __restrict__ w1rT,
                            float* __restrict__ w2lT, float* __restrict__ w2rT,
                            float* __restrict__ waT) {
    int idx = blockIdx.x * blockDim.x + threadIdx.x;
    if (idx < 16384) {
        int o = idx >> 7, c = idx & 127; w1lT[c * C_DIM + o] = w1l[idx];
    } else if (idx < 32768) {
        int j = idx - 16384; int o = j >> 7, c = j & 127; w1rT[c * C_DIM + o] = w1r[j];
    } else if (idx < 49152) {
        int j = idx - 32768; int o = j >> 7, c = j & 127; w2lT[c * C_DIM + o] = w2l[j];
    } else if (idx < 65536) {
        int j = idx - 49152; int o = j >> 7, c = j & 127; w2rT[c * C_DIM + o] = w2r[j];
    } else if (idx < 73728) {
        int j = idx - 65536; int o = j >> 7, c = j & 127; waT[c * OUT_CH + o] = wa[j];
    }
}

// ---------------- CSR build ----------------
__global__ void count_kernel(const void* __restrict__ ei, int* __restrict__ cnt) {
    int e = blockIdx.x * blockDim.x + threadIdx.x;
    if (e >= N_EDGES) return;
    int dst = load_idx(ei, N_EDGES + e, g_is64);
    atomicAdd(&cnt[dst], 1);
}

// single-block exclusive scan over 40000 counts -> offs + cursor
__global__ __launch_bounds__(1024) void scan_kernel(const int* __restrict__ cnt,
                                                    int* __restrict__ offs,
                                                    int* __restrict__ cursor) {
    __shared__ int s_part[1024];
    const int t = threadIdx.x;
    const int CH = (N_NODES + 1023) / 1024;  // 40
    const int base = t * CH;
    int sum = 0;
    for (int i = 0; i < CH; i++) {
        int idx = base + i;
        if (idx < N_NODES) sum += cnt[idx];
    }
    s_part[t] = sum;
    __syncthreads();
    for (int d = 1; d < 1024; d <<= 1) {
        int other = (t >= d) ? s_part[t - d] : 0;
        __syncthreads();
        s_part[t] += other;
        __syncthreads();
    }
    int run = s_part[t] - sum;  // exclusive prefix
    for (int i = 0; i < CH; i++) {
        int idx = base + i;
        if (idx < N_NODES) {
            offs[idx] = run;
            cursor[idx] = run;
            run += cnt[idx];
        }
    }
    if (t == 1023) offs[N_NODES] = run;
}

__global__ void fill_kernel(const void* __restrict__ ei, int* __restrict__ cursor,
                            int* __restrict__ csr_src) {
    int e = blockIdx.x * blockDim.x + threadIdx.x;
    if (e >= N_EDGES) return;
    int is64 = g_is64;
    int src = load_idx(ei, e, is64);
    int dst = load_idx(ei, N_EDGES + e, is64);
    int pos = atomicAdd(&cursor[dst], 1);
    csr_src[pos] = src;
}

// ---------------- mean aggregation: warp per node, register accumulation ----------------
__global__ __launch_bounds__(256) void gather_kernel(const int* __restrict__ offs,
                                                     const int* __restrict__ csr,
                                                     const float* __restrict__ xin,
                                                     float* __restrict__ mean) {
    int gt = blockIdx.x * blockDim.x + threadIdx.x;
    int n = gt >> 5;
    if (n >= N_NODES) return;
    int lane = gt & 31;
    int s = offs[n], e = offs[n + 1];
    float4 acc = make_float4(0.f, 0.f, 0.f, 0.f);
    int i = s;
    for (; i + 4 <= e; i += 4) {
        int s0 = __ldg(&csr[i + 0]);
        int s1 = __ldg(&csr[i + 1]);
        int s2 = __ldg(&csr[i + 2]);
        int s3 = __ldg(&csr[i + 3]);
        float4 v0 = __ldg((const float4*)(xin + (size_t)s0 * C_DIM) + lane);
        float4 v1 = __ldg((const float4*)(xin + (size_t)s1 * C_DIM) + lane);
        float4 v2 = __ldg((const float4*)(xin + (size_t)s2 * C_DIM) + lane);
        float4 v3 = __ldg((const float4*)(xin + (size_t)s3 * C_DIM) + lane);
        acc.x += v0.x + v1.x + v2.x + v3.x;
        acc.y += v0.y + v1.y + v2.y + v3.y;
        acc.z += v0.z + v1.z + v2.z + v3.z;
        acc.w += v0.w + v1.w + v2.w + v3.w;
    }
    for (; i < e; i++) {
        int s0 = __ldg(&csr[i]);
        float4 v0 = __ldg((const float4*)(xin + (size_t)s0 * C_DIM) + lane);
        acc.x += v0.x; acc.y += v0.y; acc.z += v0.z; acc.w += v0.w;
    }
    float inv = 1.0f / fmaxf((float)(e - s), 1.0f);
    ((float4*)(mean + (size_t)n * C_DIM))[lane] =
        make_float4(acc.x * inv, acc.y * inv, acc.z * inv, acc.w * inv);
}

// ---------------- fused SAGE linear (FFMA2): out = relu(mean@wl^T + bl + x@wr^T) ----
// 256 threads, 64 nodes x 128 outputs per block.
// Thread tile: 8 outputs (two float4 chunks at o and 64+o) x 4 nodes, packed f32x2.
// Activations stored duplicated-in-both-halves (u64) so a broadcast LDS.64 feeds FFMA2.
__global__ __launch_bounds__(256) void sage_kernel(
    const float* __restrict__ mean, const float* __restrict__ xin,
    const float* __restrict__ wlT, const float* __restrict__ wrT,
    const float* __restrict__ bl, float* __restrict__ out) {
    extern __shared__ unsigned char dsm[];
    unsigned long long (*s_m2)[32] = (unsigned long long(*)[32])(dsm);          // 16KB
    unsigned long long (*s_x2)[32] = (unsigned long long(*)[32])(dsm + 16384);  // 16KB
    float (*s_wl)[128] = (float(*)[128])(dsm + 32768);                          // 16KB
    float (*s_wr)[128] = (float(*)[128])(dsm + 49152);                          // 16KB

    const int t = threadIdx.x;
    const int node0 = blockIdx.x * 64;
    const int col = t & 15;
    const int row = t >> 4;
    const int o0 = col * 4;       // quarter-warp contiguous float4 -> conflict-free LDS.128
    const int o1 = 64 + col * 4;
    const int n_base = row * 4;

    unsigned long long acc2[4][4];
    {
        float4 bA = *(const float4*)&bl[o0];
        float4 bB = *(const float4*)&bl[o1];
        unsigned long long a0 = pack2(bA.x, bA.y), a1 = pack2(bA.z, bA.w);
        unsigned long long a2 = pack2(bB.x, bB.y), a3 = pack2(bB.z, bB.w);
#pragma unroll
        for (int i = 0; i < 4; i++) {
            acc2[i][0] = a0; acc2[i][1] = a1; acc2[i][2] = a2; acc2[i][3] = a3;
        }
    }

#pragma unroll 1
    for (int ct = 0; ct < C_DIM; ct += 32) {
#pragma unroll
        for (int k = 0; k < 8; k++) {
            int idx = t + k * 256;
            int n = idx >> 5, c = idx & 31;
            size_t g = (size_t)(node0 + n) * C_DIM + ct + c;
            float mv = mean[g];
            float xv = xin[g];
            s_m2[n][c] = pack2(mv, mv);
            s_x2[n][c] = pack2(xv, xv);
        }
#pragma unroll
        for (int k = 0; k < 16; k++) {
            int idx = t + k * 256;
            int c = idx >> 7, o = idx & 127;
            s_wl[c][o] = wlT[(ct + c) * C_DIM + o];
            s_wr[c][o] = wrT[(ct + c) * C_DIM + o];
        }
        __syncthreads();

#pragma unroll
        for (int cc = 0; cc < 32; cc++) {
            ulonglong2 wlA = *(const ulonglong2*)&s_wl[cc][o0];
            ulonglong2 wlB = *(const ulonglong2*)&s_wl[cc][o1];
            ulonglong2 wrA = *(const ulonglong2*)&s_wr[cc][o0];
            ulonglong2 wrB = *(const ulonglong2*)&s_wr[cc][o1];
#pragma unroll
            for (int i = 0; i < 4; i++) {
                unsigned long long m2 = s_m2[n_base + i][cc];
                unsigned long long x2 = s_x2[n_base + i][cc];
                FMA2(acc2[i][0], m2, wlA.x);
                FMA2(acc2[i][1], m2, wlA.y);
                FMA2(acc2[i][2], m2, wlB.x);
                FMA2(acc2[i][3], m2, wlB.y);
                FMA2(acc2[i][0], x2, wrA.x);
                FMA2(acc2[i][1], x2, wrA.y);
                FMA2(acc2[i][2], x2, wrB.x);
                FMA2(acc2[i][3], x2, wrB.y);
            }
        }
        __syncthreads();
    }

#pragma unroll
    for (int i = 0; i < 4; i++) {
        int n = node0 + n_base + i;
        float2 p0 = unpack2(acc2[i][0]), p1 = unpack2(acc2[i][1]);
        float2 p2 = unpack2(acc2[i][2]), p3 = unpack2(acc2[i][3]);
        float4 vA = make_float4(fmaxf(p0.x, 0.f), fmaxf(p0.y, 0.f),
                                fmaxf(p1.x, 0.f), fmaxf(p1.y, 0.f));
        float4 vB = make_float4(fmaxf(p2.x, 0.f), fmaxf(p2.y, 0.f),
                                fmaxf(p3.x, 0.f), fmaxf(p3.y, 0.f));
        *(float4*)&out[(size_t)n * C_DIM + o0] = vA;
        *(float4*)&out[(size_t)n * C_DIM + o1] = vB;
    }
}

// ---------------- head: logits = h@wa^T + ba ; values = h@wc^T + bc ----------------
// 256 threads, 64 nodes per block. 4 outputs x 4 nodes per thread.
__global__ __launch_bounds__(256) void head_kernel(
    const float* __restrict__ h,
    const float* __restrict__ waT, const float* __restrict__ ba,
    const float* __restrict__ wc, const float* __restrict__ bc,
    float* __restrict__ out) {
    extern __shared__ unsigned char dsm[];
    float (*s_h)[129] = (float(*)[129])(dsm);              // 64*129*4 = 33024 B
    float (*s_wa)[64] = (float(*)[64])(dsm + 33024);       // 128*64*4 = 32768 B

    const int t = threadIdx.x;
    const int node0 = blockIdx.x * 64;

#pragma unroll
    for (int k = 0; k < 32; k++) {
        int idx = t + k * 256;
        int n = idx >> 7, c = idx & 127;
        s_h[n][c] = h[(size_t)(node0 + n) * C_DIM + c];
        ((float*)s_wa)[idx] = waT[idx];  // s_wa is dense [128][64]
    }
    __syncthreads();

    const int col = t & 15, row = t >> 4;
    const int o_base = col * 4;
    const int n_base = row * 4;
    float4 bb = *(const float4*)&ba[o_base];
    float acc[4][4];
#pragma unroll
    for (int i = 0; i < 4; i++) {
        acc[i][0] = bb.x; acc[i][1] = bb.y; acc[i][2] = bb.z; acc[i][3] = bb.w;
    }

#pragma unroll 16
    for (int c = 0; c < C_DIM; c++) {
        float4 w = *(const float4*)&s_wa[c][o_base];
#pragma unroll
        for (int i = 0; i < 4; i++) {
            float hv = s_h[n_base + i][c];
            acc[i][0] += hv * w.x;
            acc[i][1] += hv * w.y;
            acc[i][2] += hv * w.z;
            acc[i][3] += hv * w.w;
        }
    }
#pragma unroll
    for (int i = 0; i < 4; i++) {
        int n = node0 + n_base + i;
        *(float4*)&out[(size_t)n * OUT_CH + o_base] =
            make_float4(acc[i][0], acc[i][1], acc[i][2], acc[i][3]);
    }

    // critic values: one thread per node (padded s_h -> conflict-free column walk)
    if (t < 64) {
        float v = bc[0];
#pragma unroll 16
        for (int c = 0; c < C_DIM; c++) v += s_h[t][c] * __ldg(&wc[c]);
        out[(size_t)N_NODES * OUT_CH + node0 + t] = v;
    }
}

// ---------------- launch ----------------
extern "C" void kernel_launch(void* const* d_in, const int* in_sizes, int n_in,
                              void* d_out, int out_size) {
    const float* x   = (const float*)d_in[0];
    const void*  ei  = d_in[1];
    const float* w1l = (const float*)d_in[2];
    const float* b1l = (const float*)d_in[3];
    const float* w1r = (const float*)d_in[4];
    const float* w2l = (const float*)d_in[5];
    const float* b2l = (const float*)d_in[6];
    const float* w2r = (const float*)d_in[7];
    const float* wa  = (const float*)d_in[8];
    const float* ba  = (const float*)d_in[9];
    const float* wc  = (const float*)d_in[10];
    const float* bc  = (const float*)d_in[11];
    float* out = (float*)d_out;

    float *mean, *h1, *h2, *w1lT, *w1rT, *w2lT, *w2rT, *waT;
    int *cnt, *offs, *cursor, *csr_src;
    cudaGetSymbolAddress((void**)&mean,    g_mean);
    cudaGetSymbolAddress((void**)&h1,      g_h1);
    cudaGetSymbolAddress((void**)&h2,      g_h2);
    cudaGetSymbolAddress((void**)&cnt,     g_cnt);
    cudaGetSymbolAddress((void**)&offs,    g_offs);
    cudaGetSymbolAddress((void**)&cursor,  g_cursor);
    cudaGetSymbolAddress((void**)&csr_src, g_csr_src);
    cudaGetSymbolAddress((void**)&w1lT,    g_w1lT);
    cudaGetSymbolAddress((void**)&w1rT,    g_w1rT);
    cudaGetSymbolAddress((void**)&w2lT,    g_w2lT);
    cudaGetSymbolAddress((void**)&w2rT,    g_w2rT);
    cudaGetSymbolAddress((void**)&waT,     g_waT);

    const int SAGE_SMEM = 65536;
    const int HEAD_SMEM = 33024 + 32768;
    cudaFuncSetAttribute(sage_kernel, cudaFuncAttributeMaxDynamicSharedMemorySize, SAGE_SMEM);
    cudaFuncSetAttribute(head_kernel, cudaFuncAttributeMaxDynamicSharedMemorySize, HEAD_SMEM);

    detect_kernel<<<1, 32>>>((const int*)ei);
    prep_kernel<<<(73728 + 255) / 256, 256>>>(w1l, w1r, w2l, w2r, wa,
                                              w1lT, w1rT, w2lT, w2rT, waT);

    // CSR build (graph identical for both layers)
    cudaMemsetAsync(cnt, 0, N_NODES * sizeof(int));
    count_kernel<<<(N_EDGES + 255) / 256, 256>>>(ei, cnt);
    scan_kernel<<<1, 1024>>>(cnt, offs, cursor);
    fill_kernel<<<(N_EDGES + 255) / 256, 256>>>(ei, cursor, csr_src);

    const int gather_blocks = (N_NODES * 32) / 256;  // 5000

    // ---- layer 1 ----
    gather_kernel<<<gather_blocks, 256>>>(offs, csr_src, x, mean);
    sage_kernel<<<N_NODES / 64, 256, SAGE_SMEM>>>(mean, x, w1lT, w1rT, b1l, h1);

    // ---- layer 2 ----
    gather_kernel<<<gather_blocks, 256>>>(offs, csr_src, h1, mean);
    sage_kernel<<<N_NODES / 64, 256, SAGE_SMEM>>>(mean, h1, w2lT, w2rT, b2l, h2);

    // ---- heads ----
    head_kernel<<<N_NODES / 64, 256, HEAD_SMEM>>>(h2, waT, ba, wc, bc, out);
}

// round 3
// speedup vs baseline: 2.3300x; 1.2250x over previous
#include <cuda_runtime.h>

#define N_NODES 40000
#define N_EDGES 640000
#define C_DIM   128
#define OUT_CH  64
#define BUCKET  64

// ---------------- device scratch (no allocations allowed) ----------------
__device__ float g_mean[N_NODES * C_DIM];
__device__ float g_h1[N_NODES * C_DIM];
__device__ float g_h2[N_NODES * C_DIM];
__device__ int   g_cursor[N_NODES];
__device__ int   g_csr[N_NODES * BUCKET];   // fixed-width buckets, 10.24 MB
__device__ float g_w1lT[C_DIM * C_DIM];
__device__ float g_w1rT[C_DIM * C_DIM];
__device__ float g_w2lT[C_DIM * C_DIM];
__device__ float g_w2rT[C_DIM * C_DIM];
__device__ float g_waT[C_DIM * OUT_CH];
__device__ int   g_is64;

// ---------------- packed f32x2 helpers ----------------
#define FMA2(d, a, b) asm("fma.rn.f32x2 %0, %1, %2, %0;" : "+l"(d) : "l"(a), "l"(b))

__device__ __forceinline__ unsigned long long pack2(float lo, float hi) {
    unsigned long long r;
    asm("mov.b64 %0, {%1, %2};" : "=l"(r) : "f"(lo), "f"(hi));
    return r;
}
__device__ __forceinline__ float2 unpack2(unsigned long long v) {
    float2 f;
    asm("mov.b64 {%0, %1}, %2;" : "=f"(f.x), "=f"(f.y) : "l"(v));
    return f;
}

// ---------------- index dtype detection ----------------
__global__ void detect_kernel(const int* ei) {
    if (blockIdx.x == 0 && threadIdx.x == 0) {
        bool is64 = true;
        for (int i = 0; i < 64; i++) {
            int lo = ei[2 * i];
            int hi = ei[2 * i + 1];
            if (hi != 0 || (unsigned)lo >= (unsigned)N_NODES) { is64 = false; break; }
        }
        g_is64 = is64 ? 1 : 0;
    }
}

__device__ __forceinline__ int load_idx(const void* ei, int pos, int is64) {
    if (is64) return (int)((const long long*)ei)[pos];
    return ((const int*)ei)[pos];
}

// ---------------- prep: all 5 weight transposes in one kernel ----------------
__global__ void prep_kernel(const float* __restrict__ w1l, const float* __restrict__ w1r,
                            const float* __restrict__ w2l, const float* __restrict__ w2r,
                            const float* __restrict__ wa,
                            float* __restrict__ w1lT, float* __restrict__ w1rT,
                            float* __restrict__ w2lT, float* __restrict__ w2rT,
                            float* __restrict__ waT) {
    int idx = blockIdx.x * blockDim.x + threadIdx.x;
    if (idx < 16384) {
        int o = idx >> 7, c = idx & 127; w1lT[c * C_DIM + o] = w1l[idx];
    } else if (idx < 32768) {
        int j = idx - 16384; int o = j >> 7, c = j & 127; w1rT[c * C_DIM + o] = w1r[j];
    } else if (idx < 49152) {
        int j = idx - 32768; int o = j >> 7, c = j & 127; w2lT[c * C_DIM + o] = w2l[j];
    } else if (idx < 65536) {
        int j = idx - 49152; int o = j >> 7, c = j & 127; w2rT[c * C_DIM + o] = w2r[j];
    } else if (idx < 73728) {
        int j = idx - 65536; int o = j >> 7, c = j & 127; waT[c * OUT_CH + o] = wa[j];
    }
}

// ---------------- bucketed CSR build: one pass, no scan ----------------
__global__ void fill_kernel(const void* __restrict__ ei, int* __restrict__ cursor,
                            int* __restrict__ csr) {
    int e = blockIdx.x * blockDim.x + threadIdx.x;
    if (e >= N_EDGES) return;
    int is64 = g_is64;
    int src = load_idx(ei, e, is64);
    int dst = load_idx(ei, N_EDGES + e, is64);
    int pos = atomicAdd(&cursor[dst], 1);
    if (pos < BUCKET) csr[dst * BUCKET + pos] = src;  // overflow guard (P ~ 1e-18)
}

// ---------------- mean aggregation: warp per node, register accumulation ----------------
__global__ __launch_bounds__(256) void gather_kernel(const int* __restrict__ cursor,
                                                     const int* __restrict__ csr,
                                                     const float* __restrict__ xin,
                                                     float* __restrict__ mean) {
    int gt = blockIdx.x * blockDim.x + threadIdx.x;
    int n = gt >> 5;
    if (n >= N_NODES) return;
    int lane = gt & 31;
    int deg = __ldg(&cursor[n]);
    int e = (deg < BUCKET) ? deg : BUCKET;
    const int* bkt = csr + n * BUCKET;
    float4 acc = make_float4(0.f, 0.f, 0.f, 0.f);
    int i = 0;
    for (; i + 4 <= e; i += 4) {
        int s0 = __ldg(&bkt[i + 0]);
        int s1 = __ldg(&bkt[i + 1]);
        int s2 = __ldg(&bkt[i + 2]);
        int s3 = __ldg(&bkt[i + 3]);
        float4 v0 = __ldg((const float4*)(xin + (size_t)s0 * C_DIM) + lane);
        float4 v1 = __ldg((const float4*)(xin + (size_t)s1 * C_DIM) + lane);
        float4 v2 = __ldg((const float4*)(xin + (size_t)s2 * C_DIM) + lane);
        float4 v3 = __ldg((const float4*)(xin + (size_t)s3 * C_DIM) + lane);
        acc.x += v0.x + v1.x + v2.x + v3.x;
        acc.y += v0.y + v1.y + v2.y + v3.y;
        acc.z += v0.z + v1.z + v2.z + v3.z;
        acc.w += v0.w + v1.w + v2.w + v3.w;
    }
    for (; i < e; i++) {
        int s0 = __ldg(&bkt[i]);
        float4 v0 = __ldg((const float4*)(xin + (size_t)s0 * C_DIM) + lane);
        acc.x += v0.x; acc.y += v0.y; acc.z += v0.z; acc.w += v0.w;
    }
    float inv = 1.0f / fmaxf((float)deg, 1.0f);
    ((float4*)(mean + (size_t)n * C_DIM))[lane] =
        make_float4(acc.x * inv, acc.y * inv, acc.z * inv, acc.w * inv);
}

// ---------------- fused SAGE linear (FFMA2): out = relu(mean@wl^T + bl + x@wr^T) ----
// 256 threads, 64 nodes x 128 outputs per block.
// Thread tile: 8 outputs (two float4 chunks at o and 64+o) x 4 nodes, packed f32x2.
__global__ __launch_bounds__(256) void sage_kernel(
    const float* __restrict__ mean, const float* __restrict__ xin,
    const float* __restrict__ wlT, const float* __restrict__ wrT,
    const float* __restrict__ bl, float* __restrict__ out) {
    extern __shared__ unsigned char dsm[];
    unsigned long long (*s_m2)[32] = (unsigned long long(*)[32])(dsm);          // 16KB
    unsigned long long (*s_x2)[32] = (unsigned long long(*)[32])(dsm + 16384);  // 16KB
    float (*s_wl)[128] = (float(*)[128])(dsm + 32768);                          // 16KB
    float (*s_wr)[128] = (float(*)[128])(dsm + 49152);                          // 16KB

    const int t = threadIdx.x;
    const int node0 = blockIdx.x * 64;
    const int col = t & 15;
    const int row = t >> 4;
    const int o0 = col * 4;       // quarter-warp contiguous float4 -> conflict-free LDS.128
    const int o1 = 64 + col * 4;
    const int n_base = row * 4;

    unsigned long long acc2[4][4];
    {
        float4 bA = *(const float4*)&bl[o0];
        float4 bB = *(const float4*)&bl[o1];
        unsigned long long a0 = pack2(bA.x, bA.y), a1 = pack2(bA.z, bA.w);
        unsigned long long a2 = pack2(bB.x, bB.y), a3 = pack2(bB.z, bB.w);
#pragma unroll
        for (int i = 0; i < 4; i++) {
            acc2[i][0] = a0; acc2[i][1] = a1; acc2[i][2] = a2; acc2[i][3] = a3;
        }
    }

#pragma unroll 1
    for (int ct = 0; ct < C_DIM; ct += 32) {
#pragma unroll
        for (int k = 0; k < 8; k++) {
            int idx = t + k * 256;
            int n = idx >> 5, c = idx & 31;
            size_t g = (size_t)(node0 + n) * C_DIM + ct + c;
            float mv = mean[g];
            float xv = xin[g];
            s_m2[n][c] = pack2(mv, mv);
            s_x2[n][c] = pack2(xv, xv);
        }
#pragma unroll
        for (int k = 0; k < 16; k++) {
            int idx = t + k * 256;
            int c = idx >> 7, o = idx & 127;
            s_wl[c][o] = wlT[(ct + c) * C_DIM + o];
            s_wr[c][o] = wrT[(ct + c) * C_DIM + o];
        }
        __syncthreads();

#pragma unroll
        for (int cc = 0; cc < 32; cc++) {
            ulonglong2 wlA = *(const ulonglong2*)&s_wl[cc][o0];
            ulonglong2 wlB = *(const ulonglong2*)&s_wl[cc][o1];
            ulonglong2 wrA = *(const ulonglong2*)&s_wr[cc][o0];
            ulonglong2 wrB = *(const ulonglong2*)&s_wr[cc][o1];
#pragma unroll
            for (int i = 0; i < 4; i++) {
                unsigned long long m2 = s_m2[n_base + i][cc];
                unsigned long long x2 = s_x2[n_base + i][cc];
                FMA2(acc2[i][0], m2, wlA.x);
                FMA2(acc2[i][1], m2, wlA.y);
                FMA2(acc2[i][2], m2, wlB.x);
                FMA2(acc2[i][3], m2, wlB.y);
                FMA2(acc2[i][0], x2, wrA.x);
                FMA2(acc2[i][1], x2, wrA.y);
                FMA2(acc2[i][2], x2, wrB.x);
                FMA2(acc2[i][3], x2, wrB.y);
            }
        }
        __syncthreads();
    }

#pragma unroll
    for (int i = 0; i < 4; i++) {
        int n = node0 + n_base + i;
        float2 p0 = unpack2(acc2[i][0]), p1 = unpack2(acc2[i][1]);
        float2 p2 = unpack2(acc2[i][2]), p3 = unpack2(acc2[i][3]);
        float4 vA = make_float4(fmaxf(p0.x, 0.f), fmaxf(p0.y, 0.f),
                                fmaxf(p1.x, 0.f), fmaxf(p1.y, 0.f));
        float4 vB = make_float4(fmaxf(p2.x, 0.f), fmaxf(p2.y, 0.f),
                                fmaxf(p3.x, 0.f), fmaxf(p3.y, 0.f));
        *(float4*)&out[(size_t)n * C_DIM + o0] = vA;
        *(float4*)&out[(size_t)n * C_DIM + o1] = vB;
    }
}

// ---------------- head: logits = h@wa^T + ba ; values = h@wc^T + bc ----------------
__global__ __launch_bounds__(256) void head_kernel(
    const float* __restrict__ h,
    const float* __restrict__ waT, const float* __restrict__ ba,
    const float* __restrict__ wc, const float* __restrict__ bc,
    float* __restrict__ out) {
    extern __shared__ unsigned char dsm[];
    float (*s_h)[129] = (float(*)[129])(dsm);              // 64*129*4 = 33024 B
    float (*s_wa)[64] = (float(*)[64])(dsm + 33024);       // 128*64*4 = 32768 B

    const int t = threadIdx.x;
    const int node0 = blockIdx.x * 64;

#pragma unroll
    for (int k = 0; k < 32; k++) {
        int idx = t + k * 256;
        int n = idx >> 7, c = idx & 127;
        s_h[n][c] = h[(size_t)(node0 + n) * C_DIM + c];
        ((float*)s_wa)[idx] = waT[idx];
    }
    __syncthreads();

    const int col = t & 15, row = t >> 4;
    const int o_base = col * 4;
    const int n_base = row * 4;
    float4 bb = *(const float4*)&ba[o_base];
    float acc[4][4];
#pragma unroll
    for (int i = 0; i < 4; i++) {
        acc[i][0] = bb.x; acc[i][1] = bb.y; acc[i][2] = bb.z; acc[i][3] = bb.w;
    }

#pragma unroll 16
    for (int c = 0; c < C_DIM; c++) {
        float4 w = *(const float4*)&s_wa[c][o_base];
#pragma unroll
        for (int i = 0; i < 4; i++) {
            float hv = s_h[n_base + i][c];
            acc[i][0] += hv * w.x;
            acc[i][1] += hv * w.y;
            acc[i][2] += hv * w.z;
            acc[i][3] += hv * w.w;
        }
    }
#pragma unroll
    for (int i = 0; i < 4; i++) {
        int n = node0 + n_base + i;
        *(float4*)&out[(size_t)n * OUT_CH + o_base] =
            make_float4(acc[i][0], acc[i][1], acc[i][2], acc[i][3]);
    }

    if (t < 64) {
        float v = bc[0];
#pragma unroll 16
        for (int c = 0; c < C_DIM; c++) v += s_h[t][c] * __ldg(&wc[c]);
        out[(size_t)N_NODES * OUT_CH + node0 + t] = v;
    }
}

// ---------------- launch ----------------
extern "C" void kernel_launch(void* const* d_in, const int* in_sizes, int n_in,
                              void* d_out, int out_size) {
    const float* x   = (const float*)d_in[0];
    const void*  ei  = d_in[1];
    const float* w1l = (const float*)d_in[2];
    const float* b1l = (const float*)d_in[3];
    const float* w1r = (const float*)d_in[4];
    const float* w2l = (const float*)d_in[5];
    const float* b2l = (const float*)d_in[6];
    const float* w2r = (const float*)d_in[7];
    const float* wa  = (const float*)d_in[8];
    const float* ba  = (const float*)d_in[9];
    const float* wc  = (const float*)d_in[10];
    const float* bc  = (const float*)d_in[11];
    float* out = (float*)d_out;

    float *mean, *h1, *h2, *w1lT, *w1rT, *w2lT, *w2rT, *waT;
    int *cursor, *csr;
    cudaGetSymbolAddress((void**)&mean,   g_mean);
    cudaGetSymbolAddress((void**)&h1,     g_h1);
    cudaGetSymbolAddress((void**)&h2,     g_h2);
    cudaGetSymbolAddress((void**)&cursor, g_cursor);
    cudaGetSymbolAddress((void**)&csr,    g_csr);
    cudaGetSymbolAddress((void**)&w1lT,   g_w1lT);
    cudaGetSymbolAddress((void**)&w1rT,   g_w1rT);
    cudaGetSymbolAddress((void**)&w2lT,   g_w2lT);
    cudaGetSymbolAddress((void**)&w2rT,   g_w2rT);
    cudaGetSymbolAddress((void**)&waT,    g_waT);

    const int SAGE_SMEM = 65536;
    const int HEAD_SMEM = 33024 + 32768;
    cudaFuncSetAttribute(sage_kernel, cudaFuncAttributeMaxDynamicSharedMemorySize, SAGE_SMEM);
    cudaFuncSetAttribute(head_kernel, cudaFuncAttributeMaxDynamicSharedMemorySize, HEAD_SMEM);

    detect_kernel<<<1, 32>>>((const int*)ei);
    prep_kernel<<<(73728 + 255) / 256, 256>>>(w1l, w1r, w2l, w2r, wa,
                                              w1lT, w1rT, w2lT, w2rT, waT);

    // bucketed CSR build: memset + single fill pass (no count, no scan)
    cudaMemsetAsync(cursor, 0, N_NODES * sizeof(int));
    fill_kernel<<<(N_EDGES + 255) / 256, 256>>>(ei, cursor, csr);

    const int gather_blocks = (N_NODES * 32) / 256;  // 5000

    // ---- layer 1 ----
    gather_kernel<<<gather_blocks, 256>>>(cursor, csr, x, mean);
    sage_kernel<<<N_NODES / 64, 256, SAGE_SMEM>>>(mean, x, w1lT, w1rT, b1l, h1);

    // ---- layer 2 ----
    gather_kernel<<<gather_blocks, 256>>>(cursor, csr, h1, mean);
    sage_kernel<<<N_NODES / 64, 256, SAGE_SMEM>>>(mean, h1, w2lT, w2rT, b2l, h2);

    // ---- heads ----
    head_kernel<<<N_NODES / 64, 256, HEAD_SMEM>>>(h2, waT, ba, wc, bc, out);
}

// round 5
// speedup vs baseline: 3.2347x; 1.3883x over previous
#include <cuda_runtime.h>
#include <cstdint>

#define N_NODES 40000
#define N_EDGES 640000
#define C_DIM   128
#define OUT_CH  64
#define BUCKET  64

// ---------------- device scratch (no allocations allowed) ----------------
__device__ float g_mean[N_NODES * C_DIM];
__device__ float g_h1[N_NODES * C_DIM];
__device__ float g_h2[N_NODES * C_DIM];
__device__ int   g_cursor[N_NODES];
__device__ int   g_csr[N_NODES * BUCKET];
__device__ int   g_is64;

// ---------------- helpers ----------------
__device__ __forceinline__ uint32_t f2tf(float v) {
    uint32_t r; asm("cvt.rna.tf32.f32 %0, %1;" : "=r"(r) : "f"(v)); return r;
}

__device__ __forceinline__ void mma_tf32(float& d0, float& d1, float& d2, float& d3,
                                         uint32_t a0, uint32_t a1, uint32_t a2, uint32_t a3,
                                         uint32_t b0, uint32_t b1) {
    asm volatile(
        "mma.sync.aligned.m16n8k8.row.col.f32.tf32.tf32.f32 "
        "{%0,%1,%2,%3}, {%4,%5,%6,%7}, {%8,%9}, {%0,%1,%2,%3};"
        : "+f"(d0), "+f"(d1), "+f"(d2), "+f"(d3)
        : "r"(a0), "r"(a1), "r"(a2), "r"(a3), "r"(b0), "r"(b1));
}

// ---------------- index dtype detection ----------------
__global__ void detect_kernel(const int* ei) {
    if (blockIdx.x == 0 && threadIdx.x == 0) {
        bool is64 = true;
        for (int i = 0; i < 64; i++) {
            int lo = ei[2 * i];
            int hi = ei[2 * i + 1];
            if (hi != 0 || (unsigned)lo >= (unsigned)N_NODES) { is64 = false; break; }
        }
        g_is64 = is64 ? 1 : 0;
    }
}

__device__ __forceinline__ int load_idx(const void* ei, int pos, int is64) {
    if (is64) return (int)((const long long*)ei)[pos];
    return ((const int*)ei)[pos];
}

// ---------------- bucketed CSR build ----------------
__global__ void fill_kernel(const void* __restrict__ ei, int* __restrict__ cursor,
                            int* __restrict__ csr) {
    int e = blockIdx.x * blockDim.x + threadIdx.x;
    if (e >= N_EDGES) return;
    int is64 = g_is64;
    int src = load_idx(ei, e, is64);
    int dst = load_idx(ei, N_EDGES + e, is64);
    int pos = atomicAdd(&cursor[dst], 1);
    if (pos < BUCKET) csr[dst * BUCKET + pos] = src;
}

// ---------------- mean aggregation: warp per node ----------------
__global__ __launch_bounds__(256) void gather_kernel(const int* __restrict__ cursor,
                                                     const int* __restrict__ csr,
                                                     const float* __restrict__ xin,
                                                     float* __restrict__ mean) {
    int gt = blockIdx.x * blockDim.x + threadIdx.x;
    int n = gt >> 5;
    if (n >= N_NODES) return;
    int lane = gt & 31;
    int deg = __ldg(&cursor[n]);
    int e = (deg < BUCKET) ? deg : BUCKET;
    const int* bkt = csr + n * BUCKET;
    float4 acc = make_float4(0.f, 0.f, 0.f, 0.f);
    int i = 0;
    for (; i + 4 <= e; i += 4) {
        int s0 = __ldg(&bkt[i + 0]);
        int s1 = __ldg(&bkt[i + 1]);
        int s2 = __ldg(&bkt[i + 2]);
        int s3 = __ldg(&bkt[i + 3]);
        float4 v0 = __ldg((const float4*)(xin + (size_t)s0 * C_DIM) + lane);
        float4 v1 = __ldg((const float4*)(xin + (size_t)s1 * C_DIM) + lane);
        float4 v2 = __ldg((const float4*)(xin + (size_t)s2 * C_DIM) + lane);
        float4 v3 = __ldg((const float4*)(xin + (size_t)s3 * C_DIM) + lane);
        acc.x += v0.x + v1.x + v2.x + v3.x;
        acc.y += v0.y + v1.y + v2.y + v3.y;
        acc.z += v0.z + v1.z + v2.z + v3.z;
        acc.w += v0.w + v1.w + v2.w + v3.w;
    }
    for (; i < e; i++) {
        int s0 = __ldg(&bkt[i]);
        float4 v0 = __ldg((const float4*)(xin + (size_t)s0 * C_DIM) + lane);
        acc.x += v0.x; acc.y += v0.y; acc.z += v0.z; acc.w += v0.w;
    }
    float inv = 1.0f / fmaxf((float)deg, 1.0f);
    ((float4*)(mean + (size_t)n * C_DIM))[lane] =
        make_float4(acc.x * inv, acc.y * inv, acc.z * inv, acc.w * inv);
}

// ============ tf32 mma.sync GEMM machinery ============
// smem fragment-order layouts for a 128x32 chunk:
//   A: [k8=4][m_tile=8][reg=4][lane=32]  (16 KB)
//   B: [k8=4][n_tile=16][reg=2][lane=32] (16 KB)
// m16n8k8 fragment maps:
//   A reg = (row>=8) | ((k>=4)<<1), lane = (row&7)*4 + (k&3)
//   B reg = (k>=4),                 lane = (n&7)*4 + (k&3)

// stage A chunk: rows = 128 nodes (clamped), cols = 32 k at koff
__device__ __forceinline__ void stage_A(uint32_t* sA, const float* __restrict__ src,
                                        int node0, int koff, int t) {
#pragma unroll
    for (int s = 0; s < 4; s++) {
        int idx = t + s * 256;              // 0..1023
        int r = idx >> 3;                   // 0..127
        int k = (idx & 7) << 2;             // 0,4,..,28
        int node = node0 + r;
        if (node > N_NODES - 1) node = N_NODES - 1;
        float4 v = *(const float4*)(src + (size_t)node * C_DIM + koff + k);
        int reg = ((r >> 3) & 1) | (((k >> 2) & 1) << 1);
        uint32_t off = ((((k >> 3) * 8 + (r >> 4)) * 4 + reg) * 32) + ((r & 7) << 2);
        *(uint4*)(sA + off) = make_uint4(f2tf(v.x), f2tf(v.y), f2tf(v.z), f2tf(v.w));
    }
}

// stage B chunk from weight matrix w[out][in] (row-major == K-major), 128 outs x 32 k
__device__ __forceinline__ void stage_B(uint32_t* sB, const float* __restrict__ w,
                                        int koff, int t) {
#pragma unroll
    for (int s = 0; s < 4; s++) {
        int idx = t + s * 256;
        int n = idx >> 3;
        int k = (idx & 7) << 2;
        float4 v = *(const float4*)(w + (size_t)n * C_DIM + koff + k);
        int reg = (k >> 2) & 1;
        uint32_t off = ((((k >> 3) * 16 + (n >> 3)) * 2 + reg) * 32) + ((n & 7) << 2);
        *(uint4*)(sB + off) = make_uint4(f2tf(v.x), f2tf(v.y), f2tf(v.z), f2tf(v.w));
    }
}

// stage B chunk for head: rows 0-63 = wa, row 64 = wc, rest zero
__device__ __forceinline__ void stage_B_head(uint32_t* sB, const float* __restrict__ wa,
                                             const float* __restrict__ wc,
                                             int koff, int t) {
#pragma unroll
    for (int s = 0; s < 4; s++) {
        int idx = t + s * 256;
        int n = idx >> 3;
        int k = (idx & 7) << 2;
        float4 v = make_float4(0.f, 0.f, 0.f, 0.f);
        if (n < 64)       v = *(const float4*)(wa + (size_t)n * C_DIM + koff + k);
        else if (n == 64) v = *(const float4*)(wc + koff + k);
        int reg = (k >> 2) & 1;
        uint32_t off = ((((k >> 3) * 16 + (n >> 3)) * 2 + reg) * 32) + ((n & 7) << 2);
        *(uint4*)(sB + off) = make_uint4(f2tf(v.x), f2tf(v.y), f2tf(v.z), f2tf(v.w));
    }
}

// mma over one staged 128x128x32 chunk; warp tile 64 nodes x 32 outs
__device__ __forceinline__ void mma_chunk(const uint32_t* sA, const uint32_t* sB,
                                          float acc[4][4][4], int wm, int wn, int lid) {
#pragma unroll
    for (int k8 = 0; k8 < 4; k8++) {
        uint32_t a[4][4], b[4][2];
#pragma unroll
        for (int i = 0; i < 4; i++) {
            uint32_t base = ((k8 * 8 + (wm * 4 + i)) * 4) * 32 + lid;
            a[i][0] = sA[base];      a[i][1] = sA[base + 32];
            a[i][2] = sA[base + 64]; a[i][3] = sA[base + 96];
        }
#pragma unroll
        for (int j = 0; j < 4; j++) {
            uint32_t base = ((k8 * 16 + (wn * 4 + j)) * 2) * 32 + lid;
            b[j][0] = sB[base]; b[j][1] = sB[base + 32];
        }
#pragma unroll
        for (int i = 0; i < 4; i++)
#pragma unroll
            for (int j = 0; j < 4; j++)
                mma_tf32(acc[i][j][0], acc[i][j][1], acc[i][j][2], acc[i][j][3],
                         a[i][0], a[i][1], a[i][2], a[i][3], b[j][0], b[j][1]);
    }
}

// ---------------- SAGE: out = relu([mean|x] @ [wl;wr]^T + bl) ----------------
// 256 threads = 8 warps (2 m-groups x 4 n-groups); block = 128 nodes x 128 outs.
__global__ __launch_bounds__(256, 2) void sage_mma_kernel(
    const float* __restrict__ mean, const float* __restrict__ xin,
    const float* __restrict__ wl, const float* __restrict__ wr,
    const float* __restrict__ bl, float* __restrict__ out) {
    __shared__ uint32_t sA[4096];
    __shared__ uint32_t sB[4096];
    const int t = threadIdx.x;
    const int wid = t >> 5, lid = t & 31;
    const int wm = wid >> 2, wn = wid & 3;
    const int node0 = blockIdx.x * 128;

    float acc[4][4][4];
#pragma unroll
    for (int i = 0; i < 4; i++)
#pragma unroll
        for (int j = 0; j < 4; j++) {
            acc[i][j][0] = 0.f; acc[i][j][1] = 0.f; acc[i][j][2] = 0.f; acc[i][j][3] = 0.f;
        }

#pragma unroll 1
    for (int ch = 0; ch < 8; ch++) {
        const float* Asrc = (ch < 4) ? mean : xin;
        const float* Bsrc = (ch < 4) ? wl : wr;
        int koff = (ch & 3) * 32;
        stage_A(sA, Asrc, node0, koff, t);
        stage_B(sB, Bsrc, koff, t);
        __syncthreads();
        mma_chunk(sA, sB, acc, wm, wn, lid);
        __syncthreads();
    }

    // epilogue: bias + relu, D-frag mapping: c0/c1 at (row, col/col+1), c2/c3 at row+8
    const int rbase = node0 + wm * 64 + (lid >> 2);
    const int cbase = wn * 32 + (lid & 3) * 2;
#pragma unroll
    for (int j = 0; j < 4; j++) {
        int col = cbase + j * 8;
        float b0 = __ldg(&bl[col]), b1 = __ldg(&bl[col + 1]);
#pragma unroll
        for (int i = 0; i < 4; i++) {
            int n0 = rbase + i * 16;
            if (n0 < N_NODES)
                *(float2*)(out + (size_t)n0 * C_DIM + col) =
                    make_float2(fmaxf(acc[i][j][0] + b0, 0.f), fmaxf(acc[i][j][1] + b1, 0.f));
            int n1 = n0 + 8;
            if (n1 < N_NODES)
                *(float2*)(out + (size_t)n1 * C_DIM + col) =
                    make_float2(fmaxf(acc[i][j][2] + b0, 0.f), fmaxf(acc[i][j][3] + b1, 0.f));
        }
    }
}

// ---------------- head: logits (cols 0-63) + value (col 64) ----------------
__global__ __launch_bounds__(256, 2) void head_mma_kernel(
    const float* __restrict__ h,
    const float* __restrict__ wa, const float* __restrict__ ba,
    const float* __restrict__ wc, const float* __restrict__ bc,
    float* __restrict__ out) {
    __shared__ uint32_t sA[4096];
    __shared__ uint32_t sB[4096];
    const int t = threadIdx.x;
    const int wid = t >> 5, lid = t & 31;
    const int wm = wid >> 2, wn = wid & 3;
    const int node0 = blockIdx.x * 128;

    float acc[4][4][4];
#pragma unroll
    for (int i = 0; i < 4; i++)
#pragma unroll
        for (int j = 0; j < 4; j++) {
            acc[i][j][0] = 0.f; acc[i][j][1] = 0.f; acc[i][j][2] = 0.f; acc[i][j][3] = 0.f;
        }

#pragma unroll 1
    for (int ch = 0; ch < 4; ch++) {
        int koff = ch * 32;
        stage_A(sA, h, node0, koff, t);
        stage_B_head(sB, wa, wc, koff, t);
        __syncthreads();
        mma_chunk(sA, sB, acc, wm, wn, lid);
        __syncthreads();
    }

    const int rbase = node0 + wm * 64 + (lid >> 2);
    const int cbase = wn * 32 + (lid & 3) * 2;
#pragma unroll
    for (int j = 0; j < 4; j++) {
        int col = cbase + j * 8;
        if (col < 64) {
            float b0 = __ldg(&ba[col]), b1 = __ldg(&ba[col + 1]);
#pragma unroll
            for (int i = 0; i < 4; i++) {
                int n0 = rbase + i * 16;
                if (n0 < N_NODES)
                    *(float2*)(out + (size_t)n0 * OUT_CH + col) =
                        make_float2(acc[i][j][0] + b0, acc[i][j][1] + b1);
                int n1 = n0 + 8;
                if (n1 < N_NODES)
                    *(float2*)(out + (size_t)n1 * OUT_CH + col) =
                        make_float2(acc[i][j][2] + b0, acc[i][j][3] + b1);
            }
        } else if (col == 64) {
            float b0 = __ldg(&bc[0]);
#pragma unroll
            for (int i = 0; i < 4; i++) {
                int n0 = rbase + i * 16;
                if (n0 < N_NODES)
                    out[(size_t)N_NODES * OUT_CH + n0] = acc[i][j][0] + b0;
                int n1 = n0 + 8;
                if (n1 < N_NODES)
                    out[(size_t)N_NODES * OUT_CH + n1] = acc[i][j][2] + b0;
            }
        }
    }
}

// ---------------- launch ----------------
extern "C" void kernel_launch(void* const* d_in, const int* in_sizes, int n_in,
                              void* d_out, int out_size) {
    const float* x   = (const float*)d_in[0];
    const void*  ei  = d_in[1];
    const float* w1l = (const float*)d_in[2];
    const float* b1l = (const float*)d_in[3];
    const float* w1r = (const float*)d_in[4];
    const float* w2l = (const float*)d_in[5];
    const float* b2l = (const float*)d_in[6];
    const float* w2r = (const float*)d_in[7];
    const float* wa  = (const float*)d_in[8];
    const float* ba  = (const float*)d_in[9];
    const float* wc  = (const float*)d_in[10];
    const float* bc  = (const float*)d_in[11];
    float* out = (float*)d_out;

    float *mean, *h1, *h2;
    int *cursor, *csr;
    cudaGetSymbolAddress((void**)&mean,   g_mean);
    cudaGetSymbolAddress((void**)&h1,     g_h1);
    cudaGetSymbolAddress((void**)&h2,     g_h2);
    cudaGetSymbolAddress((void**)&cursor, g_cursor);
    cudaGetSymbolAddress((void**)&csr,    g_csr);

    detect_kernel<<<1, 32>>>((const int*)ei);

    cudaMemsetAsync(cursor, 0, N_NODES * sizeof(int));
    fill_kernel<<<(N_EDGES + 255) / 256, 256>>>(ei, cursor, csr);

    const int gather_blocks = (N_NODES * 32) / 256;        // 5000
    const int gemm_blocks = (N_NODES + 127) / 128;         // 313

    // ---- layer 1 ----
    gather_kernel<<<gather_blocks, 256>>>(cursor, csr, x, mean);
    sage_mma_kernel<<<gemm_blocks, 256>>>(mean, x, w1l, w1r, b1l, h1);

    // ---- layer 2 ----
    gather_kernel<<<gather_blocks, 256>>>(cursor, csr, h1, mean);
    sage_mma_kernel<<<gemm_blocks, 256>>>(mean, h1, w2l, w2r, b2l, h2);

    // ---- heads ----
    head_mma_kernel<<<gemm_blocks, 256>>>(h2, wa, ba, wc, bc, out);
}

// round 6
// speedup vs baseline: 4.0006x; 1.2368x over previous
#include <cuda_runtime.h>
#include <cstdint>

#define N_NODES 40000
#define N_EDGES 640000
#define C_DIM   128
#define OUT_CH  64
#define BUCKET  64
#define NBLK    313          // ceil(40000/128)
#define SLAB    16384        // words per 128-row A-frag slab (128x128)

// ---------------- device scratch (no allocations allowed) ----------------
__device__ float g_h1[N_NODES * C_DIM];
__device__ float g_h2[N_NODES * C_DIM];
__device__ float g_meanF[NBLK * SLAB];
__device__ float g_xF[NBLK * SLAB];
__device__ float g_h1F[NBLK * SLAB];
__device__ float g_h2F[NBLK * SLAB];
__device__ float g_w1lF[SLAB], g_w1rF[SLAB], g_w2lF[SLAB], g_w2rF[SLAB], g_headBF[SLAB];
__device__ int   g_cursor[N_NODES];
__device__ int   g_csr[N_NODES * BUCKET];
__device__ int   g_is64;

// ---------------- helpers ----------------
__device__ __forceinline__ uint32_t f2tf(float v) {
    uint32_t r; asm("cvt.rna.tf32.f32 %0, %1;" : "=r"(r) : "f"(v)); return r;
}
__device__ __forceinline__ uint32_t smem_u32(const void* p) {
    uint32_t a;
    asm("{ .reg .u64 t; cvta.to.shared.u64 t, %1; cvt.u32.u64 %0, t; }" : "=r"(a) : "l"(p));
    return a;
}
__device__ __forceinline__ void cp16(uint32_t dst, const void* src) {
    asm volatile("cp.async.ca.shared.global [%0], [%1], 16;" :: "r"(dst), "l"(src));
}
#define CP_COMMIT() asm volatile("cp.async.commit_group;" ::: "memory")
#define CP_WAIT1()  asm volatile("cp.async.wait_group 1;" ::: "memory")
#define CP_WAIT0()  asm volatile("cp.async.wait_group 0;" ::: "memory")

__device__ __forceinline__ void mma_tf32(float& d0, float& d1, float& d2, float& d3,
                                         uint32_t a0, uint32_t a1, uint32_t a2, uint32_t a3,
                                         uint32_t b0, uint32_t b1) {
    asm volatile(
        "mma.sync.aligned.m16n8k8.row.col.f32.tf32.tf32.f32 "
        "{%0,%1,%2,%3}, {%4,%5,%6,%7}, {%8,%9}, {%0,%1,%2,%3};"
        : "+f"(d0), "+f"(d1), "+f"(d2), "+f"(d3)
        : "r"(a0), "r"(a1), "r"(a2), "r"(a3), "r"(b0), "r"(b1));
}

// mma over one staged 128x128x32 chunk; warp tile 64 nodes x 32 outs
// A chunk layout: [k8=4][m_tile=8][reg=4][lane=32]; B: [k8=4][n_tile=16][reg=2][lane=32]
__device__ __forceinline__ void mma_chunk(const uint32_t* sA, const uint32_t* sB,
                                          float acc[4][4][4], int wm, int wn, int lid) {
#pragma unroll
    for (int k8 = 0; k8 < 4; k8++) {
        uint32_t a[4][4], b[4][2];
#pragma unroll
        for (int i = 0; i < 4; i++) {
            uint32_t base = ((k8 * 8 + (wm * 4 + i)) * 4) * 32 + lid;
            a[i][0] = sA[base];      a[i][1] = sA[base + 32];
            a[i][2] = sA[base + 64]; a[i][3] = sA[base + 96];
        }
#pragma unroll
        for (int j = 0; j < 4; j++) {
            uint32_t base = ((k8 * 16 + (wn * 4 + j)) * 2) * 32 + lid;
            b[j][0] = sB[base]; b[j][1] = sB[base + 32];
        }
#pragma unroll
        for (int i = 0; i < 4; i++)
#pragma unroll
            for (int j = 0; j < 4; j++)
                mma_tf32(acc[i][j][0], acc[i][j][1], acc[i][j][2], acc[i][j][3],
                         a[i][0], a[i][1], a[i][2], a[i][3], b[j][0], b[j][1]);
    }
}

// ---------------- index dtype detection ----------------
__global__ void detect_kernel(const int* ei) {
    if (blockIdx.x == 0 && threadIdx.x == 0) {
        bool is64 = true;
        for (int i = 0; i < 64; i++) {
            int lo = ei[2 * i];
            int hi = ei[2 * i + 1];
            if (hi != 0 || (unsigned)lo >= (unsigned)N_NODES) { is64 = false; break; }
        }
        g_is64 = is64 ? 1 : 0;
    }
}
__device__ __forceinline__ int load_idx(const void* ei, int pos, int is64) {
    if (is64) return (int)((const long long*)ei)[pos];
    return ((const int*)ei)[pos];
}

// ---------------- bucketed CSR build ----------------
__global__ void fill_kernel(const void* __restrict__ ei, int* __restrict__ cursor,
                            int* __restrict__ csr) {
    int e = blockIdx.x * blockDim.x + threadIdx.x;
    if (e >= N_EDGES) return;
    int is64 = g_is64;
    int src = load_idx(ei, e, is64);
    int dst = load_idx(ei, N_EDGES + e, is64);
    int pos = atomicAdd(&cursor[dst], 1);
    if (pos < BUCKET) csr[dst * BUCKET + pos] = src;
}

// ---------------- weight prep: row-major fp32 -> B-frag tf32 ----------------
// B-frag word w: lane=w&31, reg=(w>>5)&1, ntile=(w>>6)&15, k8=w>>10
// n = ntile*8 + lane>>2 ; k = k8*8 + reg*4 + (lane&3)
__global__ void prepw_kernel(const float* __restrict__ w1l, const float* __restrict__ w1r,
                             const float* __restrict__ w2l, const float* __restrict__ w2r,
                             const float* __restrict__ wa, const float* __restrict__ wc,
                             float* __restrict__ w1lF, float* __restrict__ w1rF,
                             float* __restrict__ w2lF, float* __restrict__ w2rF,
                             float* __restrict__ headBF) {
    int gid = blockIdx.x * blockDim.x + threadIdx.x;   // 0..20479
    int m = gid >> 12, g = gid & 4095;
    int w = g * 4;
    int lane = w & 31, reg = (w >> 5) & 1, ntile = (w >> 6) & 15, k8 = w >> 10;
    int n = ntile * 8 + (lane >> 2);
    int k = k8 * 8 + reg * 4;
    float4 v = make_float4(0.f, 0.f, 0.f, 0.f);
    float* dst;
    switch (m) {
        case 0: v = __ldg((const float4*)(w1l + (size_t)n * C_DIM + k)); dst = w1lF; break;
        case 1: v = __ldg((const float4*)(w1r + (size_t)n * C_DIM + k)); dst = w1rF; break;
        case 2: v = __ldg((const float4*)(w2l + (size_t)n * C_DIM + k)); dst = w2lF; break;
        case 3: v = __ldg((const float4*)(w2r + (size_t)n * C_DIM + k)); dst = w2rF; break;
        default:
            if (n < 64)       v = __ldg((const float4*)(wa + (size_t)n * C_DIM + k));
            else if (n == 64) v = __ldg((const float4*)(wc + k));
            dst = headBF; break;
    }
    *(uint4*)(dst + w) = make_uint4(f2tf(v.x), f2tf(v.y), f2tf(v.z), f2tf(v.w));
}

// ---------------- A converter: row-major fp32 -> A-frag tf32 (per 128-row slab) ----
__global__ __launch_bounds__(256) void convertA_kernel(const float* __restrict__ src,
                                                       float* __restrict__ dstF) {
    __shared__ __align__(16) float s[128][36];
    const int t = threadIdx.x;
    const int node0 = blockIdx.x * 128;
    float* slab = dstF + (size_t)blockIdx.x * SLAB;
#pragma unroll 1
    for (int ch = 0; ch < 4; ch++) {
#pragma unroll
        for (int i = 0; i < 4; i++) {
            int idx = t + i * 256;
            int row = idx >> 3, k4 = (idx & 7) * 4;
            int node = node0 + row;
            if (node > N_NODES - 1) node = N_NODES - 1;
            float4 v = __ldg((const float4*)(src + (size_t)node * C_DIM + ch * 32 + k4));
            *(float4*)&s[row][k4] = v;
        }
        __syncthreads();
#pragma unroll
        for (int i = 0; i < 4; i++) {
            int w = (t + i * 256) * 4;   // word index within 4096-word chunk
            int lane = w & 31, reg = (w >> 5) & 3, tile = (w >> 7) & 7, k8 = w >> 10;
            int row = tile * 16 + (reg & 1) * 8 + (lane >> 2);
            int kb = k8 * 8 + ((reg >> 1) & 1) * 4;
            float4 v = *(const float4*)&s[row][kb];
            *(uint4*)(slab + ch * 4096 + w) =
                make_uint4(f2tf(v.x), f2tf(v.y), f2tf(v.z), f2tf(v.w));
        }
        __syncthreads();
    }
}

// ---------------- mean aggregation: warp per node, writes A-frag tf32 directly ----
__global__ __launch_bounds__(256) void gather_kernel(const int* __restrict__ cursor,
                                                     const int* __restrict__ csr,
                                                     const float* __restrict__ xin,
                                                     float* __restrict__ meanF) {
    int gt = blockIdx.x * blockDim.x + threadIdx.x;
    int n = gt >> 5;
    if (n >= N_NODES) return;
    int lane = gt & 31;
    int deg = __ldg(&cursor[n]);
    int e = (deg < BUCKET) ? deg : BUCKET;
    const int* bkt = csr + n * BUCKET;
    float4 acc = make_float4(0.f, 0.f, 0.f, 0.f);
    int i = 0;
    for (; i + 4 <= e; i += 4) {
        int s0 = __ldg(&bkt[i + 0]);
        int s1 = __ldg(&bkt[i + 1]);
        int s2 = __ldg(&bkt[i + 2]);
        int s3 = __ldg(&bkt[i + 3]);
        float4 v0 = __ldg((const float4*)(xin + (size_t)s0 * C_DIM) + lane);
        float4 v1 = __ldg((const float4*)(xin + (size_t)s1 * C_DIM) + lane);
        float4 v2 = __ldg((const float4*)(xin + (size_t)s2 * C_DIM) + lane);
        float4 v3 = __ldg((const float4*)(xin + (size_t)s3 * C_DIM) + lane);
        acc.x += v0.x + v1.x + v2.x + v3.x;
        acc.y += v0.y + v1.y + v2.y + v3.y;
        acc.z += v0.z + v1.z + v2.z + v3.z;
        acc.w += v0.w + v1.w + v2.w + v3.w;
    }
    for (; i < e; i++) {
        int s0 = __ldg(&bkt[i]);
        float4 v0 = __ldg((const float4*)(xin + (size_t)s0 * C_DIM) + lane);
        acc.x += v0.x; acc.y += v0.y; acc.z += v0.z; acc.w += v0.w;
    }
    float inv = 1.0f / fmaxf((float)deg, 1.0f);
    // frag write: lane holds k = 4*lane..4*lane+3 for row r = n&127
    int bm = n >> 7, r = n & 127;
    int k8 = lane >> 1;
    int reg = ((r >> 3) & 1) | ((lane & 1) << 1);
    int tile = (r >> 4) & 7;
    size_t base = (size_t)bm * SLAB + (((k8 * 8 + tile) * 4 + reg) * 32) + ((r & 7) * 4);
    *(uint4*)(meanF + base) = make_uint4(f2tf(acc.x * inv), f2tf(acc.y * inv),
                                         f2tf(acc.z * inv), f2tf(acc.w * inv));
}

// ---------------- pipelined tf32 SAGE GEMM ----------------
// 8 chunks: ch 0-3 = mean x wl (K 0..127), ch 4-7 = x x wr. cp.async double buffer.
__global__ __launch_bounds__(256, 2) void sage_pipe_kernel(
    const float* __restrict__ meanF, const float* __restrict__ xF,
    const float* __restrict__ wlF, const float* __restrict__ wrF,
    const float* __restrict__ bl, float* __restrict__ out) {
    extern __shared__ float smem[];   // 2 bufs x (A 4096 + B 4096) floats = 64KB
    uint32_t sbase = smem_u32(smem);
    const int t = threadIdx.x;
    const int wid = t >> 5, lid = t & 31;
    const int wm = wid >> 2, wn = wid & 3;
    const int bm = blockIdx.x;
    const int node0 = bm * 128;

    const float* Aslab0 = meanF + (size_t)bm * SLAB;
    const float* Aslab1 = xF + (size_t)bm * SLAB;

    float acc[4][4][4];
#pragma unroll
    for (int i = 0; i < 4; i++)
#pragma unroll
        for (int j = 0; j < 4; j++) {
            acc[i][j][0] = 0.f; acc[i][j][1] = 0.f; acc[i][j][2] = 0.f; acc[i][j][3] = 0.f;
        }

    // prologue: chunk 0 -> buf 0
    {
        const float* A = Aslab0;
        const float* B = wlF;
#pragma unroll
        for (int s = 0; s < 4; s++) {
            int o = (t + s * 256) * 4;
            cp16(sbase + o * 4, A + o);
            cp16(sbase + 16384 + o * 4, B + o);
        }
        CP_COMMIT();
    }

#pragma unroll 1
    for (int ch = 0; ch < 8; ch++) {
        if (ch < 7) {
            int nc = ch + 1;
            const float* A = ((nc < 4) ? Aslab0 : Aslab1) + (nc & 3) * 4096;
            const float* B = ((nc < 4) ? wlF : wrF) + (nc & 3) * 4096;
            uint32_t d = sbase + (uint32_t)((nc & 1) * 32768);
#pragma unroll
            for (int s = 0; s < 4; s++) {
                int o = (t + s * 256) * 4;
                cp16(d + o * 4, A + o);
                cp16(d + 16384 + o * 4, B + o);
            }
            CP_COMMIT();
            CP_WAIT1();
        } else {
            CP_WAIT0();
        }
        __syncthreads();
        const uint32_t* sA = (const uint32_t*)smem + (ch & 1) * 8192;
        const uint32_t* sB = sA + 4096;
        mma_chunk(sA, sB, acc, wm, wn, lid);
        __syncthreads();
    }

    // epilogue: bias + relu, row-major store
    const int rbase = node0 + wm * 64 + (lid >> 2);
    const int cbase = wn * 32 + (lid & 3) * 2;
#pragma unroll
    for (int j = 0; j < 4; j++) {
        int col = cbase + j * 8;
        float b0 = __ldg(&bl[col]), b1 = __ldg(&bl[col + 1]);
#pragma unroll
        for (int i = 0; i < 4; i++) {
            int n0 = rbase + i * 16;
            if (n0 < N_NODES)
                *(float2*)(out + (size_t)n0 * C_DIM + col) =
                    make_float2(fmaxf(acc[i][j][0] + b0, 0.f), fmaxf(acc[i][j][1] + b1, 0.f));
            int n1 = n0 + 8;
            if (n1 < N_NODES)
                *(float2*)(out + (size_t)n1 * C_DIM + col) =
                    make_float2(fmaxf(acc[i][j][2] + b0, 0.f), fmaxf(acc[i][j][3] + b1, 0.f));
        }
    }
}

// ---------------- pipelined head: logits (cols 0-63) + value (col 64) ----------------
__global__ __launch_bounds__(256, 2) void head_pipe_kernel(
    const float* __restrict__ hF, const float* __restrict__ headBF,
    const float* __restrict__ ba, const float* __restrict__ bc,
    float* __restrict__ out) {
    extern __shared__ float smem[];
    uint32_t sbase = smem_u32(smem);
    const int t = threadIdx.x;
    const int wid = t >> 5, lid = t & 31;
    const int wm = wid >> 2, wn = wid & 3;
    const int bm = blockIdx.x;
    const int node0 = bm * 128;
    const float* Aslab = hF + (size_t)bm * SLAB;

    float acc[4][4][4];
#pragma unroll
    for (int i = 0; i < 4; i++)
#pragma unroll
        for (int j = 0; j < 4; j++) {
            acc[i][j][0] = 0.f; acc[i][j][1] = 0.f; acc[i][j][2] = 0.f; acc[i][j][3] = 0.f;
        }

    {
#pragma unroll
        for (int s = 0; s < 4; s++) {
            int o = (t + s * 256) * 4;
            cp16(sbase + o * 4, Aslab + o);
            cp16(sbase + 16384 + o * 4, headBF + o);
        }
        CP_COMMIT();
    }
#pragma unroll 1
    for (int ch = 0; ch < 4; ch++) {
        if (ch < 3) {
            int nc = ch + 1;
            uint32_t d = sbase + (uint32_t)((nc & 1) * 32768);
#pragma unroll
            for (int s = 0; s < 4; s++) {
                int o = (t + s * 256) * 4;
                cp16(d + o * 4, Aslab + nc * 4096 + o);
                cp16(d + 16384 + o * 4, headBF + nc * 4096 + o);
            }
            CP_COMMIT();
            CP_WAIT1();
        } else {
            CP_WAIT0();
        }
        __syncthreads();
        const uint32_t* sA = (const uint32_t*)smem + (ch & 1) * 8192;
        const uint32_t* sB = sA + 4096;
        mma_chunk(sA, sB, acc, wm, wn, lid);
        __syncthreads();
    }

    const int rbase = node0 + wm * 64 + (lid >> 2);
    const int cbase = wn * 32 + (lid & 3) * 2;
#pragma unroll
    for (int j = 0; j < 4; j++) {
        int col = cbase + j * 8;
        if (col < 64) {
            float b0 = __ldg(&ba[col]), b1 = __ldg(&ba[col + 1]);
#pragma unroll
            for (int i = 0; i < 4; i++) {
                int n0 = rbase + i * 16;
                if (n0 < N_NODES)
                    *(float2*)(out + (size_t)n0 * OUT_CH + col) =
                        make_float2(acc[i][j][0] + b0, acc[i][j][1] + b1);
                int n1 = n0 + 8;
                if (n1 < N_NODES)
                    *(float2*)(out + (size_t)n1 * OUT_CH + col) =
                        make_float2(acc[i][j][2] + b0, acc[i][j][3] + b1);
            }
        } else if (col == 64) {
            float b0 = __ldg(&bc[0]);
#pragma unroll
            for (int i = 0; i < 4; i++) {
                int n0 = rbase + i * 16;
                if (n0 < N_NODES)
                    out[(size_t)N_NODES * OUT_CH + n0] = acc[i][j][0] + b0;
                int n1 = n0 + 8;
                if (n1 < N_NODES)
                    out[(size_t)N_NODES * OUT_CH + n1] = acc[i][j][2] + b0;
            }
        }
    }
}

// ---------------- launch ----------------
extern "C" void kernel_launch(void* const* d_in, const int* in_sizes, int n_in,
                              void* d_out, int out_size) {
    const float* x   = (const float*)d_in[0];
    const void*  ei  = d_in[1];
    const float* w1l = (const float*)d_in[2];
    const float* b1l = (const float*)d_in[3];
    const float* w1r = (const float*)d_in[4];
    const float* w2l = (const float*)d_in[5];
    const float* b2l = (const float*)d_in[6];
    const float* w2r = (const float*)d_in[7];
    const float* wa  = (const float*)d_in[8];
    const float* ba  = (const float*)d_in[9];
    const float* wc  = (const float*)d_in[10];
    const float* bc  = (const float*)d_in[11];
    float* out = (float*)d_out;

    float *h1, *h2, *meanF, *xF, *h1F, *h2F, *w1lF, *w1rF, *w2lF, *w2rF, *headBF;
    int *cursor, *csr;
    cudaGetSymbolAddress((void**)&h1,     g_h1);
    cudaGetSymbolAddress((void**)&h2,     g_h2);
    cudaGetSymbolAddress((void**)&meanF,  g_meanF);
    cudaGetSymbolAddress((void**)&xF,     g_xF);
    cudaGetSymbolAddress((void**)&h1F,    g_h1F);
    cudaGetSymbolAddress((void**)&h2F,    g_h2F);
    cudaGetSymbolAddress((void**)&w1lF,   g_w1lF);
    cudaGetSymbolAddress((void**)&w1rF,   g_w1rF);
    cudaGetSymbolAddress((void**)&w2lF,   g_w2lF);
    cudaGetSymbolAddress((void**)&w2rF,   g_w2rF);
    cudaGetSymbolAddress((void**)&headBF, g_headBF);
    cudaGetSymbolAddress((void**)&cursor, g_cursor);
    cudaGetSymbolAddress((void**)&csr,    g_csr);

    const int PIPE_SMEM = 65536;  // 2 x (16KB A + 16KB B)
    cudaFuncSetAttribute(sage_pipe_kernel, cudaFuncAttributeMaxDynamicSharedMemorySize, PIPE_SMEM);
    cudaFuncSetAttribute(head_pipe_kernel, cudaFuncAttributeMaxDynamicSharedMemorySize, PIPE_SMEM);

    detect_kernel<<<1, 32>>>((const int*)ei);
    prepw_kernel<<<80, 256>>>(w1l, w1r, w2l, w2r, wa, wc, w1lF, w1rF, w2lF, w2rF, headBF);

    cudaMemsetAsync(cursor, 0, N_NODES * sizeof(int));
    fill_kernel<<<(N_EDGES + 255) / 256, 256>>>(ei, cursor, csr);

    convertA_kernel<<<NBLK, 256>>>(x, xF);

    const int gather_blocks = (N_NODES * 32) / 256;  // 5000

    // ---- layer 1 ----
    gather_kernel<<<gather_blocks, 256>>>(cursor, csr, x, meanF);
    sage_pipe_kernel<<<NBLK, 256, PIPE_SMEM>>>(meanF, xF, w1lF, w1rF, b1l, h1);
    convertA_kernel<<<NBLK, 256>>>(h1, h1F);

    // ---- layer 2 ----
    gather_kernel<<<gather_blocks, 256>>>(cursor, csr, h1, meanF);
    sage_pipe_kernel<<<NBLK, 256, PIPE_SMEM>>>(meanF, h1F, w2lF, w2rF, b2l, h2);
    convertA_kernel<<<NBLK, 256>>>(h2, h2F);

    // ---- heads ----
    head_pipe_kernel<<<NBLK, 256, PIPE_SMEM>>>(h2F, headBF, ba, bc, out);
}

// round 7
// speedup vs baseline: 4.2710x; 1.0676x over previous
#include <cuda_runtime.h>
#include <cstdint>

#define N_NODES 40000
#define N_EDGES 640000
#define C_DIM   128
#define OUT_CH  64
#define BUCKET  64
#define NBLK    313          // ceil(40000/128)
#define SLAB    16384        // words per 128-row A-frag slab (128x128)

// ---------------- device scratch (no allocations allowed) ----------------
__device__ float g_h1[N_NODES * C_DIM];
__device__ float g_meanF[NBLK * SLAB];
__device__ float g_xF[NBLK * SLAB];
__device__ float g_h1F[NBLK * SLAB];
__device__ float g_h2F[NBLK * SLAB];
__device__ float g_w1lF[SLAB], g_w1rF[SLAB], g_w2lF[SLAB], g_w2rF[SLAB], g_headBF[SLAB];
__device__ int   g_cursor[N_NODES];
__device__ int   g_csr[N_NODES * BUCKET];
__device__ int   g_is64;

// ---------------- helpers ----------------
__device__ __forceinline__ uint32_t f2tf(float v) {
    uint32_t r; asm("cvt.rna.tf32.f32 %0, %1;" : "=r"(r) : "f"(v)); return r;
}
__device__ __forceinline__ uint32_t smem_u32(const void* p) {
    uint32_t a;
    asm("{ .reg .u64 t; cvta.to.shared.u64 t, %1; cvt.u32.u64 %0, t; }" : "=r"(a) : "l"(p));
    return a;
}
__device__ __forceinline__ void cp16(uint32_t dst, const void* src) {
    asm volatile("cp.async.ca.shared.global [%0], [%1], 16;" :: "r"(dst), "l"(src));
}
#define CP_COMMIT() asm volatile("cp.async.commit_group;" ::: "memory")
#define CP_WAIT1()  asm volatile("cp.async.wait_group 1;" ::: "memory")
#define CP_WAIT0()  asm volatile("cp.async.wait_group 0;" ::: "memory")

__device__ __forceinline__ void mma_tf32(float& d0, float& d1, float& d2, float& d3,
                                         uint32_t a0, uint32_t a1, uint32_t a2, uint32_t a3,
                                         uint32_t b0, uint32_t b1) {
    asm volatile(
        "mma.sync.aligned.m16n8k8.row.col.f32.tf32.tf32.f32 "
        "{%0,%1,%2,%3}, {%4,%5,%6,%7}, {%8,%9}, {%0,%1,%2,%3};"
        : "+f"(d0), "+f"(d1), "+f"(d2), "+f"(d3)
        : "r"(a0), "r"(a1), "r"(a2), "r"(a3), "r"(b0), "r"(b1));
}

// mma over one staged 128x128x32 chunk; warp tile 64 nodes x 32 outs
// A chunk layout: [k8=4][m_tile=8][reg=4][lane=32]; B: [k8=4][n_tile=16][reg=2][lane=32]
__device__ __forceinline__ void mma_chunk(const uint32_t* sA, const uint32_t* sB,
                                          float acc[4][4][4], int wm, int wn, int lid) {
#pragma unroll
    for (int k8 = 0; k8 < 4; k8++) {
        uint32_t a[4][4], b[4][2];
#pragma unroll
        for (int i = 0; i < 4; i++) {
            uint32_t base = ((k8 * 8 + (wm * 4 + i)) * 4) * 32 + lid;
            a[i][0] = sA[base];      a[i][1] = sA[base + 32];
            a[i][2] = sA[base + 64]; a[i][3] = sA[base + 96];
        }
#pragma unroll
        for (int j = 0; j < 4; j++) {
            uint32_t base = ((k8 * 16 + (wn * 4 + j)) * 2) * 32 + lid;
            b[j][0] = sB[base]; b[j][1] = sB[base + 32];
        }
#pragma unroll
        for (int i = 0; i < 4; i++)
#pragma unroll
            for (int j = 0; j < 4; j++)
                mma_tf32(acc[i][j][0], acc[i][j][1], acc[i][j][2], acc[i][j][3],
                         a[i][0], a[i][1], a[i][2], a[i][3], b[j][0], b[j][1]);
    }
}

// ---------------- index dtype detection ----------------
__global__ void detect_kernel(const int* ei) {
    if (blockIdx.x == 0 && threadIdx.x == 0) {
        bool is64 = true;
        for (int i = 0; i < 64; i++) {
            int lo = ei[2 * i];
            int hi = ei[2 * i + 1];
            if (hi != 0 || (unsigned)lo >= (unsigned)N_NODES) { is64 = false; break; }
        }
        g_is64 = is64 ? 1 : 0;
    }
}
__device__ __forceinline__ int load_idx(const void* ei, int pos, int is64) {
    if (is64) return (int)((const long long*)ei)[pos];
    return ((const int*)ei)[pos];
}

// ---------------- bucketed CSR build ----------------
__global__ void fill_kernel(const void* __restrict__ ei, int* __restrict__ cursor,
                            int* __restrict__ csr) {
    int e = blockIdx.x * blockDim.x + threadIdx.x;
    if (e >= N_EDGES) return;
    int is64 = g_is64;
    int src = load_idx(ei, e, is64);
    int dst = load_idx(ei, N_EDGES + e, is64);
    int pos = atomicAdd(&cursor[dst], 1);
    if (pos < BUCKET) csr[dst * BUCKET + pos] = src;
}

// ---------------- weight prep: row-major fp32 -> B-frag tf32 ----------------
__global__ void prepw_kernel(const float* __restrict__ w1l, const float* __restrict__ w1r,
                             const float* __restrict__ w2l, const float* __restrict__ w2r,
                             const float* __restrict__ wa, const float* __restrict__ wc,
                             float* __restrict__ w1lF, float* __restrict__ w1rF,
                             float* __restrict__ w2lF, float* __restrict__ w2rF,
                             float* __restrict__ headBF) {
    int gid = blockIdx.x * blockDim.x + threadIdx.x;   // 0..20479
    int m = gid >> 12, g = gid & 4095;
    int w = g * 4;
    int lane = w & 31, reg = (w >> 5) & 1, ntile = (w >> 6) & 15, k8 = w >> 10;
    int n = ntile * 8 + (lane >> 2);
    int k = k8 * 8 + reg * 4;
    float4 v = make_float4(0.f, 0.f, 0.f, 0.f);
    float* dst;
    switch (m) {
        case 0: v = __ldg((const float4*)(w1l + (size_t)n * C_DIM + k)); dst = w1lF; break;
        case 1: v = __ldg((const float4*)(w1r + (size_t)n * C_DIM + k)); dst = w1rF; break;
        case 2: v = __ldg((const float4*)(w2l + (size_t)n * C_DIM + k)); dst = w2lF; break;
        case 3: v = __ldg((const float4*)(w2r + (size_t)n * C_DIM + k)); dst = w2rF; break;
        default:
            if (n < 64)       v = __ldg((const float4*)(wa + (size_t)n * C_DIM + k));
            else if (n == 64) v = __ldg((const float4*)(wc + k));
            dst = headBF; break;
    }
    *(uint4*)(dst + w) = make_uint4(f2tf(v.x), f2tf(v.y), f2tf(v.z), f2tf(v.w));
}

// ---------------- A converter: one 128x32 chunk per block (grid = NBLK*4) ----------
__global__ __launch_bounds__(256) void convertA_kernel(const float* __restrict__ src,
                                                       float* __restrict__ dstF) {
    __shared__ __align__(16) float s[128][36];
    const int t = threadIdx.x;
    const int bm = blockIdx.x >> 2;
    const int ch = blockIdx.x & 3;
    const int node0 = bm * 128;
    float* slab = dstF + (size_t)bm * SLAB;
#pragma unroll
    for (int i = 0; i < 4; i++) {
        int idx = t + i * 256;
        int row = idx >> 3, k4 = (idx & 7) * 4;
        int node = node0 + row;
        if (node > N_NODES - 1) node = N_NODES - 1;
        float4 v = __ldg((const float4*)(src + (size_t)node * C_DIM + ch * 32 + k4));
        *(float4*)&s[row][k4] = v;
    }
    __syncthreads();
#pragma unroll
    for (int i = 0; i < 4; i++) {
        int w = (t + i * 256) * 4;   // word index within 4096-word chunk
        int lane = w & 31, reg = (w >> 5) & 3, tile = (w >> 7) & 7, k8 = w >> 10;
        int row = tile * 16 + (reg & 1) * 8 + (lane >> 2);
        int kb = k8 * 8 + ((reg >> 1) & 1) * 4;
        float4 v = *(const float4*)&s[row][kb];
        *(uint4*)(slab + ch * 4096 + w) =
            make_uint4(f2tf(v.x), f2tf(v.y), f2tf(v.z), f2tf(v.w));
    }
}

// ---------------- mean aggregation: warp per node, writes A-frag tf32 directly ----
__global__ __launch_bounds__(256) void gather_kernel(const int* __restrict__ cursor,
                                                     const int* __restrict__ csr,
                                                     const float* __restrict__ xin,
                                                     float* __restrict__ meanF) {
    int gt = blockIdx.x * blockDim.x + threadIdx.x;
    int n = gt >> 5;
    if (n >= N_NODES) return;
    int lane = gt & 31;
    int deg = __ldg(&cursor[n]);
    int e = (deg < BUCKET) ? deg : BUCKET;
    const int* bkt = csr + n * BUCKET;
    float4 acc = make_float4(0.f, 0.f, 0.f, 0.f);
    int i = 0;
    for (; i + 4 <= e; i += 4) {
        int s0 = __ldg(&bkt[i + 0]);
        int s1 = __ldg(&bkt[i + 1]);
        int s2 = __ldg(&bkt[i + 2]);
        int s3 = __ldg(&bkt[i + 3]);
        float4 v0 = __ldg((const float4*)(xin + (size_t)s0 * C_DIM) + lane);
        float4 v1 = __ldg((const float4*)(xin + (size_t)s1 * C_DIM) + lane);
        float4 v2 = __ldg((const float4*)(xin + (size_t)s2 * C_DIM) + lane);
        float4 v3 = __ldg((const float4*)(xin + (size_t)s3 * C_DIM) + lane);
        acc.x += v0.x + v1.x + v2.x + v3.x;
        acc.y += v0.y + v1.y + v2.y + v3.y;
        acc.z += v0.z + v1.z + v2.z + v3.z;
        acc.w += v0.w + v1.w + v2.w + v3.w;
    }
    for (; i < e; i++) {
        int s0 = __ldg(&bkt[i]);
        float4 v0 = __ldg((const float4*)(xin + (size_t)s0 * C_DIM) + lane);
        acc.x += v0.x; acc.y += v0.y; acc.z += v0.z; acc.w += v0.w;
    }
    float inv = 1.0f / fmaxf((float)deg, 1.0f);
    // frag write: lane holds k = 4*lane..4*lane+3 for row r = n&127
    int bm = n >> 7, r = n & 127;
    int k8 = lane >> 1;
    int reg = ((r >> 3) & 1) | ((lane & 1) << 1);
    int tile = (r >> 4) & 7;
    size_t base = (size_t)bm * SLAB + (((k8 * 8 + tile) * 4 + reg) * 32) + ((r & 7) * 4);
    *(uint4*)(meanF + base) = make_uint4(f2tf(acc.x * inv), f2tf(acc.y * inv),
                                         f2tf(acc.z * inv), f2tf(acc.w * inv));
}

// ---------------- pipelined tf32 SAGE GEMM + fused epilogue conversion ----------
// 8 chunks: ch 0-3 = mean x wl, ch 4-7 = x x wr. cp.async double buffer.
// Epilogue stages relu(acc+bias) into smem [128][132], then writes row-major
// output (if requested) AND the A-frag tf32 slab for the next GEMM.
__global__ __launch_bounds__(256, 2) void sage_pipe_kernel(
    const float* __restrict__ meanF, const float* __restrict__ xF,
    const float* __restrict__ wlF, const float* __restrict__ wrF,
    const float* __restrict__ bl,
    float* __restrict__ out_rm,      // row-major output (may be null)
    float* __restrict__ outF) {      // A-frag tf32 output slab array
    extern __shared__ float smem[];   // max(64KB pipe, 128*132*4=67584B epilogue)
    uint32_t sbase = smem_u32(smem);
    const int t = threadIdx.x;
    const int wid = t >> 5, lid = t & 31;
    const int wm = wid >> 2, wn = wid & 3;
    const int bm = blockIdx.x;
    const int node0 = bm * 128;

    const float* Aslab0 = meanF + (size_t)bm * SLAB;
    const float* Aslab1 = xF + (size_t)bm * SLAB;

    float acc[4][4][4];
#pragma unroll
    for (int i = 0; i < 4; i++)
#pragma unroll
        for (int j = 0; j < 4; j++) {
            acc[i][j][0] = 0.f; acc[i][j][1] = 0.f; acc[i][j][2] = 0.f; acc[i][j][3] = 0.f;
        }

    // prologue: chunk 0 -> buf 0
    {
#pragma unroll
        for (int s = 0; s < 4; s++) {
            int o = (t + s * 256) * 4;
            cp16(sbase + o * 4, Aslab0 + o);
            cp16(sbase + 16384 + o * 4, wlF + o);
        }
        CP_COMMIT();
    }

#pragma unroll 1
    for (int ch = 0; ch < 8; ch++) {
        if (ch < 7) {
            int nc = ch + 1;
            const float* A = ((nc < 4) ? Aslab0 : Aslab1) + (nc & 3) * 4096;
            const float* B = ((nc < 4) ? wlF : wrF) + (nc & 3) * 4096;
            uint32_t d = sbase + (uint32_t)((nc & 1) * 32768);
#pragma unroll
            for (int s = 0; s < 4; s++) {
                int o = (t + s * 256) * 4;
                cp16(d + o * 4, A + o);
                cp16(d + 16384 + o * 4, B + o);
            }
            CP_COMMIT();
            CP_WAIT1();
        } else {
            CP_WAIT0();
        }
        __syncthreads();
        const uint32_t* sA = (const uint32_t*)smem + (ch & 1) * 8192;
        const uint32_t* sB = sA + 4096;
        mma_chunk(sA, sB, acc, wm, wn, lid);
        __syncthreads();
    }

    // ---- fused epilogue: stage relu(acc+bias) into smem [128][132] ----
    const int lrow = wm * 64 + (lid >> 2);          // local row 0..127
    const int cbase = wn * 32 + (lid & 3) * 2;
#pragma unroll
    for (int j = 0; j < 4; j++) {
        int col = cbase + j * 8;
        float b0 = __ldg(&bl[col]), b1 = __ldg(&bl[col + 1]);
#pragma unroll
        for (int i = 0; i < 4; i++) {
            int r0 = lrow + i * 16;
            smem[r0 * 132 + col]     = fmaxf(acc[i][j][0] + b0, 0.f);
            smem[r0 * 132 + col + 1] = fmaxf(acc[i][j][1] + b1, 0.f);
            smem[(r0 + 8) * 132 + col]     = fmaxf(acc[i][j][2] + b0, 0.f);
            smem[(r0 + 8) * 132 + col + 1] = fmaxf(acc[i][j][3] + b1, 0.f);
        }
    }
    __syncthreads();

    // row-major store (coalesced), only if needed
    if (out_rm) {
#pragma unroll
        for (int i = 0; i < 16; i++) {
            int idx = t + i * 256;                  // 0..4095 float4s
            int row = idx >> 5, c4 = (idx & 31) * 4;
            int node = node0 + row;
            if (node < N_NODES)
                *(float4*)(out_rm + (size_t)node * C_DIM + c4) =
                    *(const float4*)&smem[row * 132 + c4];
        }
    }

    // A-frag tf32 store for the next GEMM
    float* slab = outF + (size_t)bm * SLAB;
#pragma unroll
    for (int i = 0; i < 16; i++) {
        int w = (t + i * 256) * 4;                  // word index 0..16383
        int lane = w & 31, reg = (w >> 5) & 3, tile = (w >> 7) & 7, k8c = w >> 10;
        int row = tile * 16 + (reg & 1) * 8 + (lane >> 2);
        int kb = k8c * 8 + ((reg >> 1) & 1) * 4;
        float4 v = *(const float4*)&smem[row * 132 + kb];
        *(uint4*)(slab + w) = make_uint4(f2tf(v.x), f2tf(v.y), f2tf(v.z), f2tf(v.w));
    }
}

// ---------------- pipelined head: logits (cols 0-63) + value (col 64) ----------------
__global__ __launch_bounds__(256, 2) void head_pipe_kernel(
    const float* __restrict__ hF, const float* __restrict__ headBF,
    const float* __restrict__ ba, const float* __restrict__ bc,
    float* __restrict__ out) {
    extern __shared__ float smem[];
    uint32_t sbase = smem_u32(smem);
    const int t = threadIdx.x;
    const int wid = t >> 5, lid = t & 31;
    const int wm = wid >> 2, wn = wid & 3;
    const int bm = blockIdx.x;
    const int node0 = bm * 128;
    const float* Aslab = hF + (size_t)bm * SLAB;

    float acc[4][4][4];
#pragma unroll
    for (int i = 0; i < 4; i++)
#pragma unroll
        for (int j = 0; j < 4; j++) {
            acc[i][j][0] = 0.f; acc[i][j][1] = 0.f; acc[i][j][2] = 0.f; acc[i][j][3] = 0.f;
        }

    {
#pragma unroll
        for (int s = 0; s < 4; s++) {
            int o = (t + s * 256) * 4;
            cp16(sbase + o * 4, Aslab + o);
            cp16(sbase + 16384 + o * 4, headBF + o);
        }
        CP_COMMIT();
    }
#pragma unroll 1
    for (int ch = 0; ch < 4; ch++) {
        if (ch < 3) {
            int nc = ch + 1;
            uint32_t d = sbase + (uint32_t)((nc & 1) * 32768);
#pragma unroll
            for (int s = 0; s < 4; s++) {
                int o = (t + s * 256) * 4;
                cp16(d + o * 4, Aslab + nc * 4096 + o);
                cp16(d + 16384 + o * 4, headBF + nc * 4096 + o);
            }
            CP_COMMIT();
            CP_WAIT1();
        } else {
            CP_WAIT0();
        }
        __syncthreads();
        const uint32_t* sA = (const uint32_t*)smem + (ch & 1) * 8192;
        const uint32_t* sB = sA + 4096;
        mma_chunk(sA, sB, acc, wm, wn, lid);
        __syncthreads();
    }

    const int rbase = node0 + wm * 64 + (lid >> 2);
    const int cbase = wn * 32 + (lid & 3) * 2;
#pragma unroll
    for (int j = 0; j < 4; j++) {
        int col = cbase + j * 8;
        if (col < 64) {
            float b0 = __ldg(&ba[col]), b1 = __ldg(&ba[col + 1]);
#pragma unroll
            for (int i = 0; i < 4; i++) {
                int n0 = rbase + i * 16;
                if (n0 < N_NODES)
                    *(float2*)(out + (size_t)n0 * OUT_CH + col) =
                        make_float2(acc[i][j][0] + b0, acc[i][j][1] + b1);
                int n1 = n0 + 8;
                if (n1 < N_NODES)
                    *(float2*)(out + (size_t)n1 * OUT_CH + col) =
                        make_float2(acc[i][j][2] + b0, acc[i][j][3] + b1);
            }
        } else if (col == 64) {
            float b0 = __ldg(&bc[0]);
#pragma unroll
            for (int i = 0; i < 4; i++) {
                int n0 = rbase + i * 16;
                if (n0 < N_NODES)
                    out[(size_t)N_NODES * OUT_CH + n0] = acc[i][j][0] + b0;
                int n1 = n0 + 8;
                if (n1 < N_NODES)
                    out[(size_t)N_NODES * OUT_CH + n1] = acc[i][j][2] + b0;
            }
        }
    }
}

// ---------------- launch ----------------
extern "C" void kernel_launch(void* const* d_in, const int* in_sizes, int n_in,
                              void* d_out, int out_size) {
    const float* x   = (const float*)d_in[0];
    const void*  ei  = d_in[1];
    const float* w1l = (const float*)d_in[2];
    const float* b1l = (const float*)d_in[3];
    const float* w1r = (const float*)d_in[4];
    const float* w2l = (const float*)d_in[5];
    const float* b2l = (const float*)d_in[6];
    const float* w2r = (const float*)d_in[7];
    const float* wa  = (const float*)d_in[8];
    const float* ba  = (const float*)d_in[9];
    const float* wc  = (const float*)d_in[10];
    const float* bc  = (const float*)d_in[11];
    float* out = (float*)d_out;

    float *h1, *meanF, *xF, *h1F, *h2F, *w1lF, *w1rF, *w2lF, *w2rF, *headBF;
    int *cursor, *csr;
    cudaGetSymbolAddress((void**)&h1,     g_h1);
    cudaGetSymbolAddress((void**)&meanF,  g_meanF);
    cudaGetSymbolAddress((void**)&xF,     g_xF);
    cudaGetSymbolAddress((void**)&h1F,    g_h1F);
    cudaGetSymbolAddress((void**)&h2F,    g_h2F);
    cudaGetSymbolAddress((void**)&w1lF,   g_w1lF);
    cudaGetSymbolAddress((void**)&w1rF,   g_w1rF);
    cudaGetSymbolAddress((void**)&w2lF,   g_w2lF);
    cudaGetSymbolAddress((void**)&w2rF,   g_w2rF);
    cudaGetSymbolAddress((void**)&headBF, g_headBF);
    cudaGetSymbolAddress((void**)&cursor, g_cursor);
    cudaGetSymbolAddress((void**)&csr,    g_csr);

    const int SAGE_SMEM = 128 * 132 * 4;  // 67584 >= 64KB pipeline needs
    const int HEAD_SMEM = 65536;
    cudaFuncSetAttribute(sage_pipe_kernel, cudaFuncAttributeMaxDynamicSharedMemorySize, SAGE_SMEM);
    cudaFuncSetAttribute(head_pipe_kernel, cudaFuncAttributeMaxDynamicSharedMemorySize, HEAD_SMEM);

    detect_kernel<<<1, 32>>>((const int*)ei);
    prepw_kernel<<<80, 256>>>(w1l, w1r, w2l, w2r, wa, wc, w1lF, w1rF, w2lF, w2rF, headBF);

    cudaMemsetAsync(cursor, 0, N_NODES * sizeof(int));
    fill_kernel<<<(N_EDGES + 255) / 256, 256>>>(ei, cursor, csr);

    convertA_kernel<<<NBLK * 4, 256>>>(x, xF);

    const int gather_blocks = (N_NODES * 32) / 256;  // 5000

    // ---- layer 1 ----
    gather_kernel<<<gather_blocks, 256>>>(cursor, csr, x, meanF);
    sage_pipe_kernel<<<NBLK, 256, SAGE_SMEM>>>(meanF, xF, w1lF, w1rF, b1l, h1, h1F);

    // ---- layer 2 (row-major h2 has no consumer -> frag only) ----
    gather_kernel<<<gather_blocks, 256>>>(cursor, csr, h1, meanF);
    sage_pipe_kernel<<<NBLK, 256, SAGE_SMEM>>>(meanF, h1F, w2lF, w2rF, b2l, nullptr, h2F);

    // ---- heads ----
    head_pipe_kernel<<<NBLK, 256, HEAD_SMEM>>>(h2F, headBF, ba, bc, out);
}

// round 8
// speedup vs baseline: 4.4643x; 1.0453x over previous
#include <cuda_runtime.h>
#include <cuda_fp16.h>
#include <cstdint>

#define N_NODES 40000
#define N_EDGES 640000
#define C_DIM   128
#define OUT_CH  64
#define BUCKET  64
#define NBLK    313          // ceil(40000/128)
#define SLAB    16384        // words per 128-row A-frag slab (128x128)

// ---------------- device scratch (no allocations allowed) ----------------
__device__ __half g_xH[N_NODES * C_DIM];    // fp16 copy of x for gather
__device__ __half g_h1H[N_NODES * C_DIM];   // fp16 copy of h1 for gather
__device__ float g_meanF[NBLK * SLAB];
__device__ float g_xF[NBLK * SLAB];
__device__ float g_h1F[NBLK * SLAB];
__device__ float g_h2F[NBLK * SLAB];
__device__ float g_w1lF[SLAB], g_w1rF[SLAB], g_w2lF[SLAB], g_w2rF[SLAB], g_headBF[SLAB];
__device__ int   g_cursor[N_NODES];
__device__ int   g_csr[N_NODES * BUCKET];
__device__ int   g_is64;

// ---------------- helpers ----------------
__device__ __forceinline__ uint32_t f2tf(float v) {
    uint32_t r; asm("cvt.rna.tf32.f32 %0, %1;" : "=r"(r) : "f"(v)); return r;
}
__device__ __forceinline__ uint32_t smem_u32(const void* p) {
    uint32_t a;
    asm("{ .reg .u64 t; cvta.to.shared.u64 t, %1; cvt.u32.u64 %0, t; }" : "=r"(a) : "l"(p));
    return a;
}
__device__ __forceinline__ void cp16(uint32_t dst, const void* src) {
    asm volatile("cp.async.ca.shared.global [%0], [%1], 16;" :: "r"(dst), "l"(src));
}
#define CP_COMMIT() asm volatile("cp.async.commit_group;" ::: "memory")
#define CP_WAIT1()  asm volatile("cp.async.wait_group 1;" ::: "memory")
#define CP_WAIT0()  asm volatile("cp.async.wait_group 0;" ::: "memory")

__device__ __forceinline__ uint2 pack_half4(float a, float b, float c, float d) {
    __half2 h01 = __floats2half2_rn(a, b);
    __half2 h23 = __floats2half2_rn(c, d);
    uint2 p;
    p.x = *(uint32_t*)&h01;
    p.y = *(uint32_t*)&h23;
    return p;
}

__device__ __forceinline__ void mma_tf32(float& d0, float& d1, float& d2, float& d3,
                                         uint32_t a0, uint32_t a1, uint32_t a2, uint32_t a3,
                                         uint32_t b0, uint32_t b1) {
    asm volatile(
        "mma.sync.aligned.m16n8k8.row.col.f32.tf32.tf32.f32 "
        "{%0,%1,%2,%3}, {%4,%5,%6,%7}, {%8,%9}, {%0,%1,%2,%3};"
        : "+f"(d0), "+f"(d1), "+f"(d2), "+f"(d3)
        : "r"(a0), "r"(a1), "r"(a2), "r"(a3), "r"(b0), "r"(b1));
}

// mma over one staged 128x128x32 chunk; warp tile 64 nodes x 32 outs
// A chunk layout: [k8=4][m_tile=8][reg=4][lane=32]; B: [k8=4][n_tile=16][reg=2][lane=32]
__device__ __forceinline__ void mma_chunk(const uint32_t* sA, const uint32_t* sB,
                                          float acc[4][4][4], int wm, int wn, int lid) {
#pragma unroll
    for (int k8 = 0; k8 < 4; k8++) {
        uint32_t a[4][4], b[4][2];
#pragma unroll
        for (int i = 0; i < 4; i++) {
            uint32_t base = ((k8 * 8 + (wm * 4 + i)) * 4) * 32 + lid;
            a[i][0] = sA[base];      a[i][1] = sA[base + 32];
            a[i][2] = sA[base + 64]; a[i][3] = sA[base + 96];
        }
#pragma unroll
        for (int j = 0; j < 4; j++) {
            uint32_t base = ((k8 * 16 + (wn * 4 + j)) * 2) * 32 + lid;
            b[j][0] = sB[base]; b[j][1] = sB[base + 32];
        }
#pragma unroll
        for (int i = 0; i < 4; i++)
#pragma unroll
            for (int j = 0; j < 4; j++)
                mma_tf32(acc[i][j][0], acc[i][j][1], acc[i][j][2], acc[i][j][3],
                         a[i][0], a[i][1], a[i][2], a[i][3], b[j][0], b[j][1]);
    }
}

// ---------------- index dtype detection ----------------
__global__ void detect_kernel(const int* ei) {
    if (blockIdx.x == 0 && threadIdx.x == 0) {
        bool is64 = true;
        for (int i = 0; i < 64; i++) {
            int lo = ei[2 * i];
            int hi = ei[2 * i + 1];
            if (hi != 0 || (unsigned)lo >= (unsigned)N_NODES) { is64 = false; break; }
        }
        g_is64 = is64 ? 1 : 0;
    }
}
__device__ __forceinline__ int load_idx(const void* ei, int pos, int is64) {
    if (is64) return (int)((const long long*)ei)[pos];
    return ((const int*)ei)[pos];
}

// ---------------- bucketed CSR build ----------------
__global__ void fill_kernel(const void* __restrict__ ei, int* __restrict__ cursor,
                            int* __restrict__ csr) {
    int e = blockIdx.x * blockDim.x + threadIdx.x;
    if (e >= N_EDGES) return;
    int is64 = g_is64;
    int src = load_idx(ei, e, is64);
    int dst = load_idx(ei, N_EDGES + e, is64);
    int pos = atomicAdd(&cursor[dst], 1);
    if (pos < BUCKET) csr[dst * BUCKET + pos] = src;
}

// ---------------- weight prep: row-major fp32 -> B-frag tf32 ----------------
__global__ void prepw_kernel(const float* __restrict__ w1l, const float* __restrict__ w1r,
                             const float* __restrict__ w2l, const float* __restrict__ w2r,
                             const float* __restrict__ wa, const float* __restrict__ wc,
                             float* __restrict__ w1lF, float* __restrict__ w1rF,
                             float* __restrict__ w2lF, float* __restrict__ w2rF,
                             float* __restrict__ headBF) {
    int gid = blockIdx.x * blockDim.x + threadIdx.x;   // 0..20479
    int m = gid >> 12, g = gid & 4095;
    int w = g * 4;
    int lane = w & 31, reg = (w >> 5) & 1, ntile = (w >> 6) & 15, k8 = w >> 10;
    int n = ntile * 8 + (lane >> 2);
    int k = k8 * 8 + reg * 4;
    float4 v = make_float4(0.f, 0.f, 0.f, 0.f);
    float* dst;
    switch (m) {
        case 0: v = __ldg((const float4*)(w1l + (size_t)n * C_DIM + k)); dst = w1lF; break;
        case 1: v = __ldg((const float4*)(w1r + (size_t)n * C_DIM + k)); dst = w1rF; break;
        case 2: v = __ldg((const float4*)(w2l + (size_t)n * C_DIM + k)); dst = w2lF; break;
        case 3: v = __ldg((const float4*)(w2r + (size_t)n * C_DIM + k)); dst = w2rF; break;
        default:
            if (n < 64)       v = __ldg((const float4*)(wa + (size_t)n * C_DIM + k));
            else if (n == 64) v = __ldg((const float4*)(wc + k));
            dst = headBF; break;
    }
    *(uint4*)(dst + w) = make_uint4(f2tf(v.x), f2tf(v.y), f2tf(v.z), f2tf(v.w));
}

// ---------------- A converter: one 128x32 chunk per block (grid = NBLK*4) ----------
// Also emits the fp16 copy (xH) for the gather kernels.
__global__ __launch_bounds__(256) void convertA_kernel(const float* __restrict__ src,
                                                       float* __restrict__ dstF,
                                                       __half* __restrict__ dstH) {
    __shared__ __align__(16) float s[128][36];
    const int t = threadIdx.x;
    const int bm = blockIdx.x >> 2;
    const int ch = blockIdx.x & 3;
    const int node0 = bm * 128;
    float* slab = dstF + (size_t)bm * SLAB;
#pragma unroll
    for (int i = 0; i < 4; i++) {
        int idx = t + i * 256;
        int row = idx >> 3, k4 = (idx & 7) * 4;
        int node = node0 + row;
        bool valid = (node < N_NODES);
        if (!valid) node = N_NODES - 1;
        float4 v = __ldg((const float4*)(src + (size_t)node * C_DIM + ch * 32 + k4));
        *(float4*)&s[row][k4] = v;
        if (valid)
            *(uint2*)(dstH + (size_t)node * C_DIM + ch * 32 + k4) =
                pack_half4(v.x, v.y, v.z, v.w);
    }
    __syncthreads();
#pragma unroll
    for (int i = 0; i < 4; i++) {
        int w = (t + i * 256) * 4;   // word index within 4096-word chunk
        int lane = w & 31, reg = (w >> 5) & 3, tile = (w >> 7) & 7, k8 = w >> 10;
        int row = tile * 16 + (reg & 1) * 8 + (lane >> 2);
        int kb = k8 * 8 + ((reg >> 1) & 1) * 4;
        float4 v = *(const float4*)&s[row][kb];
        *(uint4*)(slab + ch * 4096 + w) =
            make_uint4(f2tf(v.x), f2tf(v.y), f2tf(v.z), f2tf(v.w));
    }
}

// ---------------- mean aggregation: warp per node, fp16 sources, fp32 accum ----
__global__ __launch_bounds__(256) void gather_kernel(const int* __restrict__ cursor,
                                                     const int* __restrict__ csr,
                                                     const __half* __restrict__ xh,
                                                     float* __restrict__ meanF) {
    int gt = blockIdx.x * blockDim.x + threadIdx.x;
    int n = gt >> 5;
    if (n >= N_NODES) return;
    int lane = gt & 31;
    int deg = __ldg(&cursor[n]);
    int e = (deg < BUCKET) ? deg : BUCKET;
    const int* bkt = csr + n * BUCKET;
    float4 acc = make_float4(0.f, 0.f, 0.f, 0.f);
    int i = 0;
    for (; i + 4 <= e; i += 4) {
        int s0 = __ldg(&bkt[i + 0]);
        int s1 = __ldg(&bkt[i + 1]);
        int s2 = __ldg(&bkt[i + 2]);
        int s3 = __ldg(&bkt[i + 3]);
        uint2 u0 = __ldg((const uint2*)(xh + (size_t)s0 * C_DIM) + lane);
        uint2 u1 = __ldg((const uint2*)(xh + (size_t)s1 * C_DIM) + lane);
        uint2 u2 = __ldg((const uint2*)(xh + (size_t)s2 * C_DIM) + lane);
        uint2 u3 = __ldg((const uint2*)(xh + (size_t)s3 * C_DIM) + lane);
        float2 a0 = __half22float2(*(__half2*)&u0.x), b0 = __half22float2(*(__half2*)&u0.y);
        float2 a1 = __half22float2(*(__half2*)&u1.x), b1 = __half22float2(*(__half2*)&u1.y);
        float2 a2 = __half22float2(*(__half2*)&u2.x), b2 = __half22float2(*(__half2*)&u2.y);
        float2 a3 = __half22float2(*(__half2*)&u3.x), b3 = __half22float2(*(__half2*)&u3.y);
        acc.x += a0.x + a1.x + a2.x + a3.x;
        acc.y += a0.y + a1.y + a2.y + a3.y;
        acc.z += b0.x + b1.x + b2.x + b3.x;
        acc.w += b0.y + b1.y + b2.y + b3.y;
    }
    for (; i < e; i++) {
        int s0 = __ldg(&bkt[i]);
        uint2 u0 = __ldg((const uint2*)(xh + (size_t)s0 * C_DIM) + lane);
        float2 a0 = __half22float2(*(__half2*)&u0.x), b0 = __half22float2(*(__half2*)&u0.y);
        acc.x += a0.x; acc.y += a0.y; acc.z += b0.x; acc.w += b0.y;
    }
    float inv = 1.0f / fmaxf((float)deg, 1.0f);
    // frag write: lane holds k = 4*lane..4*lane+3 for row r = n&127
    int bm = n >> 7, r = n & 127;
    int k8 = lane >> 1;
    int reg = ((r >> 3) & 1) | ((lane & 1) << 1);
    int tile = (r >> 4) & 7;
    size_t base = (size_t)bm * SLAB + (((k8 * 8 + tile) * 4 + reg) * 32) + ((r & 7) * 4);
    *(uint4*)(meanF + base) = make_uint4(f2tf(acc.x * inv), f2tf(acc.y * inv),
                                         f2tf(acc.z * inv), f2tf(acc.w * inv));
}

// ---------------- pipelined tf32 SAGE GEMM + fused epilogue conversion ----------
// 8 chunks: ch 0-3 = mean x wl, ch 4-7 = x x wr. cp.async double buffer.
// Epilogue stages relu(acc+bias) into smem [128][132], then writes the fp16
// row-major copy (for the next gather, if any) AND the A-frag tf32 slab.
__global__ __launch_bounds__(256, 2) void sage_pipe_kernel(
    const float* __restrict__ meanF, const float* __restrict__ xF,
    const float* __restrict__ wlF, const float* __restrict__ wrF,
    const float* __restrict__ bl,
    __half* __restrict__ out_h,      // fp16 row-major output (may be null)
    float* __restrict__ outF) {      // A-frag tf32 output slab array
    extern __shared__ float smem[];   // max(64KB pipe, 128*132*4=67584B epilogue)
    uint32_t sbase = smem_u32(smem);
    const int t = threadIdx.x;
    const int wid = t >> 5, lid = t & 31;
    const int wm = wid >> 2, wn = wid & 3;
    const int bm = blockIdx.x;
    const int node0 = bm * 128;

    const float* Aslab0 = meanF + (size_t)bm * SLAB;
    const float* Aslab1 = xF + (size_t)bm * SLAB;

    float acc[4][4][4];
#pragma unroll
    for (int i = 0; i < 4; i++)
#pragma unroll
        for (int j = 0; j < 4; j++) {
            acc[i][j][0] = 0.f; acc[i][j][1] = 0.f; acc[i][j][2] = 0.f; acc[i][j][3] = 0.f;
        }

    // prologue: chunk 0 -> buf 0
    {
#pragma unroll
        for (int s = 0; s < 4; s++) {
            int o = (t + s * 256) * 4;
            cp16(sbase + o * 4, Aslab0 + o);
            cp16(sbase + 16384 + o * 4, wlF + o);
        }
        CP_COMMIT();
    }

#pragma unroll 1
    for (int ch = 0; ch < 8; ch++) {
        if (ch < 7) {
            int nc = ch + 1;
            const float* A = ((nc < 4) ? Aslab0 : Aslab1) + (nc & 3) * 4096;
            const float* B = ((nc < 4) ? wlF : wrF) + (nc & 3) * 4096;
            uint32_t d = sbase + (uint32_t)((nc & 1) * 32768);
#pragma unroll
            for (int s = 0; s < 4; s++) {
                int o = (t + s * 256) * 4;
                cp16(d + o * 4, A + o);
                cp16(d + 16384 + o * 4, B + o);
            }
            CP_COMMIT();
            CP_WAIT1();
        } else {
            CP_WAIT0();
        }
        __syncthreads();
        const uint32_t* sA = (const uint32_t*)smem + (ch & 1) * 8192;
        const uint32_t* sB = sA + 4096;
        mma_chunk(sA, sB, acc, wm, wn, lid);
        __syncthreads();
    }

    // ---- fused epilogue: stage relu(acc+bias) into smem [128][132] ----
    const int lrow = wm * 64 + (lid >> 2);          // local row 0..127
    const int cbase = wn * 32 + (lid & 3) * 2;
#pragma unroll
    for (int j = 0; j < 4; j++) {
        int col = cbase + j * 8;
        float b0 = __ldg(&bl[col]), b1 = __ldg(&bl[col + 1]);
#pragma unroll
        for (int i = 0; i < 4; i++) {
            int r0 = lrow + i * 16;
            smem[r0 * 132 + col]     = fmaxf(acc[i][j][0] + b0, 0.f);
            smem[r0 * 132 + col + 1] = fmaxf(acc[i][j][1] + b1, 0.f);
            smem[(r0 + 8) * 132 + col]     = fmaxf(acc[i][j][2] + b0, 0.f);
            smem[(r0 + 8) * 132 + col + 1] = fmaxf(acc[i][j][3] + b1, 0.f);
        }
    }
    __syncthreads();

    // fp16 row-major store (coalesced), only if a later gather consumes it
    if (out_h) {
#pragma unroll
        for (int i = 0; i < 16; i++) {
            int idx = t + i * 256;                  // 0..4095 half4 chunks
            int row = idx >> 5, c4 = (idx & 31) * 4;
            int node = node0 + row;
            if (node < N_NODES) {
                const float* p = &smem[row * 132 + c4];
                *(uint2*)(out_h + (size_t)node * C_DIM + c4) =
                    pack_half4(p[0], p[1], p[2], p[3]);
            }
        }
    }

    // A-frag tf32 store for the next GEMM
    float* slab = outF + (size_t)bm * SLAB;
#pragma unroll
    for (int i = 0; i < 16; i++) {
        int w = (t + i * 256) * 4;                  // word index 0..16383
        int lane = w & 31, reg = (w >> 5) & 3, tile = (w >> 7) & 7, k8c = w >> 10;
        int row = tile * 16 + (reg & 1) * 8 + (lane >> 2);
        int kb = k8c * 8 + ((reg >> 1) & 1) * 4;
        float4 v = *(const float4*)&smem[row * 132 + kb];
        *(uint4*)(slab + w) = make_uint4(f2tf(v.x), f2tf(v.y), f2tf(v.z), f2tf(v.w));
    }
}

// ---------------- pipelined head: logits (cols 0-63) + value (col 64) ----------------
__global__ __launch_bounds__(256, 2) void head_pipe_kernel(
    const float* __restrict__ hF, const float* __restrict__ headBF,
    const float* __restrict__ ba, const float* __restrict__ bc,
    float* __restrict__ out) {
    extern __shared__ float smem[];
    uint32_t sbase = smem_u32(smem);
    const int t = threadIdx.x;
    const int wid = t >> 5, lid = t & 31;
    const int wm = wid >> 2, wn = wid & 3;
    const int bm = blockIdx.x;
    const int node0 = bm * 128;
    const float* Aslab = hF + (size_t)bm * SLAB;

    float acc[4][4][4];
#pragma unroll
    for (int i = 0; i < 4; i++)
#pragma unroll
        for (int j = 0; j < 4; j++) {
            acc[i][j][0] = 0.f; acc[i][j][1] = 0.f; acc[i][j][2] = 0.f; acc[i][j][3] = 0.f;
        }

    {
#pragma unroll
        for (int s = 0; s < 4; s++) {
            int o = (t + s * 256) * 4;
            cp16(sbase + o * 4, Aslab + o);
            cp16(sbase + 16384 + o * 4, headBF + o);
        }
        CP_COMMIT();
    }
#pragma unroll 1
    for (int ch = 0; ch < 4; ch++) {
        if (ch < 3) {
            int nc = ch + 1;
            uint32_t d = sbase + (uint32_t)((nc & 1) * 32768);
#pragma unroll
            for (int s = 0; s < 4; s++) {
                int o = (t + s * 256) * 4;
                cp16(d + o * 4, Aslab + nc * 4096 + o);
                cp16(d + 16384 + o * 4, headBF + nc * 4096 + o);
            }
            CP_COMMIT();
            CP_WAIT1();
        } else {
            CP_WAIT0();
        }
        __syncthreads();
        const uint32_t* sA = (const uint32_t*)smem + (ch & 1) * 8192;
        const uint32_t* sB = sA + 4096;
        mma_chunk(sA, sB, acc, wm, wn, lid);
        __syncthreads();
    }

    const int rbase = node0 + wm * 64 + (lid >> 2);
    const int cbase = wn * 32 + (lid & 3) * 2;
#pragma unroll
    for (int j = 0; j < 4; j++) {
        int col = cbase + j * 8;
        if (col < 64) {
            float b0 = __ldg(&ba[col]), b1 = __ldg(&ba[col + 1]);
#pragma unroll
            for (int i = 0; i < 4; i++) {
                int n0 = rbase + i * 16;
                if (n0 < N_NODES)
                    *(float2*)(out + (size_t)n0 * OUT_CH + col) =
                        make_float2(acc[i][j][0] + b0, acc[i][j][1] + b1);
                int n1 = n0 + 8;
                if (n1 < N_NODES)
                    *(float2*)(out + (size_t)n1 * OUT_CH + col) =
                        make_float2(acc[i][j][2] + b0, acc[i][j][3] + b1);
            }
        } else if (col == 64) {
            float b0 = __ldg(&bc[0]);
#pragma unroll
            for (int i = 0; i < 4; i++) {
                int n0 = rbase + i * 16;
                if (n0 < N_NODES)
                    out[(size_t)N_NODES * OUT_CH + n0] = acc[i][j][0] + b0;
                int n1 = n0 + 8;
                if (n1 < N_NODES)
                    out[(size_t)N_NODES * OUT_CH + n1] = acc[i][j][2] + b0;
            }
        }
    }
}

// ---------------- launch ----------------
extern "C" void kernel_launch(void* const* d_in, const int* in_sizes, int n_in,
                              void* d_out, int out_size) {
    const float* x   = (const float*)d_in[0];
    const void*  ei  = d_in[1];
    const float* w1l = (const float*)d_in[2];
    const float* b1l = (const float*)d_in[3];
    const float* w1r = (const float*)d_in[4];
    const float* w2l = (const float*)d_in[5];
    const float* b2l = (const float*)d_in[6];
    const float* w2r = (const float*)d_in[7];
    const float* wa  = (const float*)d_in[8];
    const float* ba  = (const float*)d_in[9];
    const float* wc  = (const float*)d_in[10];
    const float* bc  = (const float*)d_in[11];
    float* out = (float*)d_out;

    float *meanF, *xF, *h1F, *h2F, *w1lF, *w1rF, *w2lF, *w2rF, *headBF;
    __half *xH, *h1H;
    int *cursor, *csr;
    cudaGetSymbolAddress((void**)&xH,     g_xH);
    cudaGetSymbolAddress((void**)&h1H,    g_h1H);
    cudaGetSymbolAddress((void**)&meanF,  g_meanF);
    cudaGetSymbolAddress((void**)&xF,     g_xF);
    cudaGetSymbolAddress((void**)&h1F,    g_h1F);
    cudaGetSymbolAddress((void**)&h2F,    g_h2F);
    cudaGetSymbolAddress((void**)&w1lF,   g_w1lF);
    cudaGetSymbolAddress((void**)&w1rF,   g_w1rF);
    cudaGetSymbolAddress((void**)&w2lF,   g_w2lF);
    cudaGetSymbolAddress((void**)&w2rF,   g_w2rF);
    cudaGetSymbolAddress((void**)&headBF, g_headBF);
    cudaGetSymbolAddress((void**)&cursor, g_cursor);
    cudaGetSymbolAddress((void**)&csr,    g_csr);

    const int SAGE_SMEM = 128 * 132 * 4;  // 67584 >= 64KB pipeline needs
    const int HEAD_SMEM = 65536;
    cudaFuncSetAttribute(sage_pipe_kernel, cudaFuncAttributeMaxDynamicSharedMemorySize, SAGE_SMEM);
    cudaFuncSetAttribute(head_pipe_kernel, cudaFuncAttributeMaxDynamicSharedMemorySize, HEAD_SMEM);

    detect_kernel<<<1, 32>>>((const int*)ei);
    prepw_kernel<<<80, 256>>>(w1l, w1r, w2l, w2r, wa, wc, w1lF, w1rF, w2lF, w2rF, headBF);

    cudaMemsetAsync(cursor, 0, N_NODES * sizeof(int));
    fill_kernel<<<(N_EDGES + 255) / 256, 256>>>(ei, cursor, csr);

    convertA_kernel<<<NBLK * 4, 256>>>(x, xF, xH);

    const int gather_blocks = (N_NODES * 32) / 256;  // 5000

    // ---- layer 1 ----
    gather_kernel<<<gather_blocks, 256>>>(cursor, csr, xH, meanF);
    sage_pipe_kernel<<<NBLK, 256, SAGE_SMEM>>>(meanF, xF, w1lF, w1rF, b1l, h1H, h1F);

    // ---- layer 2 (h2 row-major has no consumer -> frag only) ----
    gather_kernel<<<gather_blocks, 256>>>(cursor, csr, h1H, meanF);
    sage_pipe_kernel<<<NBLK, 256, SAGE_SMEM>>>(meanF, h1F, w2lF, w2rF, b2l, nullptr, h2F);

    // ---- heads ----
    head_pipe_kernel<<<NBLK, 256, HEAD_SMEM>>>(h2F, headBF, ba, bc, out);
}